// round 12
// baseline (speedup 1.0000x reference)
#include <cuda_runtime.h>
#include <cstdint>

// ---------------- scratch (allocation-free rule: __device__ globals) ----------
// g_q/g_k/g_v : [B,H,N,64] (tf32-rounded; q pre-scaled by 0.125)
// g_vt : [B,H,64,N] (V transposed)   g_ao : [B,N,768] (tf32-rounded)
// g_xr/g_wr/g_w2r : rna-rounded copies of x / qkv_w / out_w (cp.async can't round)
__device__ float g_q[2 * 12 * 2048 * 64];
__device__ float g_k[2 * 12 * 2048 * 64];
__device__ float g_v[2 * 12 * 2048 * 64];
__device__ float g_vt[2 * 12 * 64 * 2048];
__device__ float g_ao[2 * 2048 * 768];
__device__ float g_xr[2 * 2048 * 768];
__device__ float g_wr[768 * 2304];
__device__ float g_w2r[768 * 768];
__device__ float g_mneg[2 * 2048];                  // 0 or -1e30 per key
__device__ unsigned char g_dist8[2 * 2048 * 2048];  // clipped dist, 1 byte

__device__ __forceinline__ float to_tf32(float x) {
    float r;
    asm("cvt.rna.tf32.f32 %0, %1;" : "=f"(r) : "f"(x));
    return r;
}
__device__ __forceinline__ void mma8(float* c, const uint32_t* a, const uint32_t* b) {
    asm("mma.sync.aligned.m16n8k8.row.col.f32.tf32.tf32.f32 "
        "{%0,%1,%2,%3},{%4,%5,%6,%7},{%8,%9},{%0,%1,%2,%3};"
        : "+f"(c[0]), "+f"(c[1]), "+f"(c[2]), "+f"(c[3])
        : "r"(a[0]), "r"(a[1]), "r"(a[2]), "r"(a[3]), "r"(b[0]), "r"(b[1]));
}
__device__ __forceinline__ uint32_t smem_u32(const void* p) {
    uint32_t a;
    asm("{ .reg .u64 t; cvta.to.shared.u64 t, %1; cvt.u32.u64 %0, t; }" : "=r"(a) : "l"(p));
    return a;
}
// tf32 fragments via b16 ldmatrix: lane l <- (row l/4, col l%4) per 8x4-tf32 tile
__device__ __forceinline__ void ldsm4(uint32_t* r, uint32_t addr) {
    asm volatile("ldmatrix.sync.aligned.m8n8.x4.shared.b16 {%0,%1,%2,%3}, [%4];"
                 : "=r"(r[0]), "=r"(r[1]), "=r"(r[2]), "=r"(r[3]) : "r"(addr));
}
__device__ __forceinline__ void cpa16(uint32_t saddr, const void* g) {
    asm volatile("cp.async.cg.shared.global [%0], [%1], 16;" :: "r"(saddr), "l"(g));
}
#define CP_COMMIT() asm volatile("cp.async.commit_group;" ::: "memory")
#define CP_WAIT0()  asm volatile("cp.async.wait_group 0;" ::: "memory")

// =============================================================================
// Kernel 0a: mask dtype sniffer + conversion (validated R3)
// =============================================================================
__global__ void mask_prep(const unsigned int* __restrict__ mw) {
    const int tid = threadIdx.x;
    int ok_int = 1, ok_flt = 1;
    for (int i = tid; i < 1024; i += 256) {
        unsigned int v = mw[i];
        if (v != 0u && v != 1u) ok_int = 0;
        if (v != 0u && v != 0x3F800000u) ok_flt = 0;
    }
    ok_int = __syncthreads_and(ok_int);
    ok_flt = __syncthreads_and(ok_flt);
    if (ok_int) {
        const int* m = (const int*)mw;
        for (int i = tid; i < 4096; i += 256) g_mneg[i] = m[i] ? -1e30f : 0.0f;
    } else if (ok_flt) {
        const float* m = (const float*)mw;
        for (int i = tid; i < 4096; i += 256) g_mneg[i] = (m[i] != 0.0f) ? -1e30f : 0.0f;
    } else {
        const unsigned char* m = (const unsigned char*)mw;
        for (int i = tid; i < 4096; i += 256) g_mneg[i] = m[i] ? -1e30f : 0.0f;
    }
}

// =============================================================================
// Kernel 0b: pack dist int32 -> clipped uint8 (validated R6)
// =============================================================================
__global__ void dist_pack(const int* __restrict__ dist) {
    size_t i = ((size_t)blockIdx.x * 256 + threadIdx.x) * 8;
    int4 a = *(const int4*)(dist + i);
    int4 b = *(const int4*)(dist + i + 4);
    unsigned c0 = (unsigned)min(max(a.x, 0), 31) | ((unsigned)min(max(a.y, 0), 31) << 8) |
                  ((unsigned)min(max(a.z, 0), 31) << 16) | ((unsigned)min(max(a.w, 0), 31) << 24);
    unsigned c1 = (unsigned)min(max(b.x, 0), 31) | ((unsigned)min(max(b.y, 0), 31) << 8) |
                  ((unsigned)min(max(b.z, 0), 31) << 16) | ((unsigned)min(max(b.w, 0), 31) << 24);
    *(uint2*)(g_dist8 + i) = make_uint2(c0, c1);
}

// =============================================================================
// Kernel 0c (NEW R12): rna-round a tensor into tf32 scratch.
// cp.async staging in gemm_tc truncates (RZ) — one-sided bias pushed rel_err
// to 9.4e-4 in R11. Pre-rounding restores R8's zero-mean numerics.
// =============================================================================
__global__ void round_tf32_k(const float* __restrict__ src, int n, int which) {
    float* dst = (which == 0) ? g_xr : (which == 1 ? g_wr : g_w2r);
    int i = (blockIdx.x * 256 + threadIdx.x) * 4;
    if (i < n) {
        float4 v = *(const float4*)(src + i);
        *(float4*)(dst + i) =
            make_float4(to_tf32(v.x), to_tf32(v.y), to_tf32(v.z), to_tf32(v.w));
    }
}

// =============================================================================
// Kernel 1: tf32 tensor-core GEMM v2 (validated R11) — cp.async + LDSM A-frags.
// A/W now come from rna-rounded device scratch (R12 precision fix).
// =============================================================================
__global__ __launch_bounds__(256) void gemm_tc(const float* __restrict__ A,
                                               const float* __restrict__ W,
                                               const float* __restrict__ Bv,
                                               float* __restrict__ outp,
                                               int N, int mode) {
    if (mode == 0) { A = g_xr; W = g_wr; }   // device-side symbols (R7 lesson)
    else           { A = g_ao; W = g_w2r; }
    __shared__ float As[2][128][20];   // [m][k], 80B pitch (16B-aligned, LDSM-ok)
    __shared__ float Bs[2][16][136];
    const int tid = threadIdx.x, w = tid >> 5, l = tid & 31;
    const int gid = l >> 2, tig = l & 3;
    const int wm = w >> 2, wn = w & 3;
    const int bM = blockIdx.y * 128, bN = blockIdx.x * 128;
    const uint32_t sb_a = smem_u32(&As[0][0][0]);
    const uint32_t sb_b = smem_u32(&Bs[0][0][0]);

    auto stage = [&](int k0, int buf) {
#pragma unroll
        for (int j = 0; j < 2; j++) {  // A: 128 rows x 64B
            int c = tid + j * 256, r = c >> 2, o = c & 3;
            cpa16(sb_a + buf * 10240 + r * 80 + o * 16,
                  A + (size_t)(bM + r) * 768 + k0 + o * 4);
        }
#pragma unroll
        for (int j = 0; j < 2; j++) {  // B: 16 rows x 512B
            int c = tid + j * 256, r = c >> 5, o = c & 31;
            cpa16(sb_b + buf * 8704 + r * 544 + o * 16,
                  W + (size_t)(k0 + r) * N + bN + o * 4);
        }
    };

    float acc[4][4][4];
#pragma unroll
    for (int mi = 0; mi < 4; mi++)
#pragma unroll
        for (int ni = 0; ni < 4; ni++)
#pragma unroll
            for (int j = 0; j < 4; j++) acc[mi][ni][j] = 0.f;

    const uint32_t prowA = (l & 7) + ((l >> 3) & 1) * 8;
    const uint32_t pcolA = ((l >> 4) & 1) * 4;

    stage(0, 0);
    CP_COMMIT();

    for (int ks = 0; ks < 48; ks++) {
        CP_WAIT0();
        __syncthreads();  // tile ks visible; ks-1 drained
        if (ks < 47) { stage((ks + 1) * 16, (ks + 1) & 1); CP_COMMIT(); }
        const int buf = ks & 1;
        const uint32_t abase = sb_a + buf * 10240;

#pragma unroll
        for (int kk = 0; kk < 2; kk++) {
            const int kb = kk * 8;
            uint32_t Af[4][4], Bf[4][2];
#pragma unroll
            for (int mi = 0; mi < 4; mi++) {
                const int m0 = wm * 64 + mi * 16;
                ldsm4(Af[mi], abase + (m0 + prowA) * 80 + (kb + pcolA) * 4);
            }
#pragma unroll
            for (int ni = 0; ni < 4; ni++) {
                const int n0 = wn * 32 + ni * 8 + gid;
                Bf[ni][0] = __float_as_uint(Bs[buf][kb + tig][n0]);
                Bf[ni][1] = __float_as_uint(Bs[buf][kb + tig + 4][n0]);
            }
#pragma unroll
            for (int mi = 0; mi < 4; mi++)
#pragma unroll
                for (int ni = 0; ni < 4; ni++) mma8(acc[mi][ni], Af[mi], Bf[ni]);
        }
    }

    // ---- epilogue (validated R8)
#pragma unroll
    for (int ni = 0; ni < 4; ni++) {
        const int col0 = bN + wn * 32 + ni * 8 + tig * 2;
        const float b0 = Bv[col0], b1 = Bv[col0 + 1];
        if (mode == 0) {
            const int which = col0 / 768;
            const int rem = col0 % 768;
            const int hh = rem / 64, hd0 = rem % 64;
            float* dst = (which == 0) ? g_q : (which == 1 ? g_k : g_v);
            const float qs = (which == 0) ? 0.125f : 1.0f;
#pragma unroll
            for (int mi = 0; mi < 4; mi++) {
                const int row = bM + wm * 64 + mi * 16 + gid;
                const int bidx = row >> 11, n = row & 2047;
                float* p = dst + ((((size_t)bidx * 12 + hh) * 2048 + n) * 64 + hd0);
                *(float2*)p = make_float2(to_tf32((acc[mi][ni][0] + b0) * qs),
                                          to_tf32((acc[mi][ni][1] + b1) * qs));
                const int row2 = row + 8;
                const int bidx2 = row2 >> 11, n2 = row2 & 2047;
                float* p2 = dst + ((((size_t)bidx2 * 12 + hh) * 2048 + n2) * 64 + hd0);
                *(float2*)p2 = make_float2(to_tf32((acc[mi][ni][2] + b0) * qs),
                                           to_tf32((acc[mi][ni][3] + b1) * qs));
            }
        } else {
#pragma unroll
            for (int mi = 0; mi < 4; mi++) {
                const int row = bM + wm * 64 + mi * 16 + gid;
                *(float2*)(outp + (size_t)row * 768 + col0) =
                    make_float2(acc[mi][ni][0] + b0, acc[mi][ni][1] + b1);
                *(float2*)(outp + (size_t)(row + 8) * 768 + col0) =
                    make_float2(acc[mi][ni][2] + b0, acc[mi][ni][3] + b1);
            }
        }
    }
}

// =============================================================================
// Kernel 1b: transpose V -> g_vt [B,H,64,N] (validated R9)
// =============================================================================
__global__ __launch_bounds__(256) void v_transpose() {
    __shared__ float sm[64 * 65];
    const int n0 = blockIdx.x * 64;
    const int bh = blockIdx.y;
    const float* src = g_v + ((size_t)bh * 2048 + n0) * 64;
    for (int v = threadIdx.x; v < 1024; v += 256) {
        int i = v >> 4, d4 = (v & 15) << 2;
        float4 t = *(const float4*)(src + i * 64 + d4);
        sm[(d4 + 0) * 65 + i] = t.x; sm[(d4 + 1) * 65 + i] = t.y;
        sm[(d4 + 2) * 65 + i] = t.z; sm[(d4 + 3) * 65 + i] = t.w;
    }
    __syncthreads();
    float* dst = g_vt + (size_t)bh * 64 * 2048 + n0;
    for (int v = threadIdx.x; v < 1024; v += 256) {
        int d = v >> 4, j4 = (v & 15) << 2;
        *(float4*)(dst + (size_t)d * 2048 + j4) =
            make_float4(sm[d * 65 + j4], sm[d * 65 + j4 + 1],
                        sm[d * 65 + j4 + 2], sm[d * 65 + j4 + 3]);
    }
}

// =============================================================================
// Kernel 2: tf32 mma.sync flash attention — barrier-diet (validated R11).
// Epilogue now tf32-rounds g_ao (proj GEMM A input; R12 precision fix).
// =============================================================================
static constexpr int VT_REL = 17408;          // Vt offset within a stage
static constexpr int MNG_REL = 34816;         // mask offset within a stage
static constexpr int STG_SZ = 35072;          // K[64][68] + Vt[64][68] + mng[64]
static constexpr int DS_OFF = 70144;          // dist [128 q][64] u8 = 8192
static constexpr int PS_OFF = 78336;          // P [128 q][68] f32 = 34816
static constexpr int BT_OFF = 113152;         // 32 f32
static constexpr int ATTN_SMEM = 113280;      // <= 114688 -> 2 CTAs/SM

__global__ __launch_bounds__(256, 2) void attn_mma(const float* __restrict__ bias_table) {
    extern __shared__ char smem[];
    const uint32_t sb = smem_u32(smem);
    unsigned char* Ds = (unsigned char*)(smem + DS_OFF);
    float* Ps = (float*)(smem + PS_OFF);
    float* btc = (float*)(smem + BT_OFF);

    const int tid = threadIdx.x, w = tid >> 5, l = tid & 31;
    const int gid = l >> 2, tig = l & 3;
    const int qt = blockIdx.x, h = blockIdx.y, b = blockIdx.z;
    const size_t bh = (size_t)b * 12 + h;

    const char* kgbase = (const char*)(g_k + (bh * 2048) * 64);
    const char* vgbase = (const char*)(g_vt + bh * 131072);
    const unsigned char* dgbase = g_dist8 + (size_t)(b * 2048 + qt * 128) * 2048;

    auto stage_kv = [&](int kt, int buf) {
        const uint32_t base = sb + buf * STG_SZ;
#pragma unroll
        for (int j = 0; j < 4; j++) {
            int c = tid + j * 256, r = c >> 4, o = (c & 15) * 16;
            cpa16(base + r * 272 + o, kgbase + ((size_t)(kt * 64 + r) * 256) + o);
        }
#pragma unroll
        for (int j = 0; j < 4; j++) {
            int c = tid + j * 256, r = c >> 4, o = (c & 15) * 16;
            cpa16(base + VT_REL + r * 272 + o, vgbase + ((size_t)r * 8192) + kt * 256 + o);
        }
        if (tid < 16) cpa16(base + MNG_REL + tid * 16, g_mneg + b * 2048 + kt * 64 + tid * 4);
    };
    auto stage_dm = [&](int kt) {
#pragma unroll
        for (int j = 0; j < 2; j++) {
            int c = l + j * 32, r = w * 16 + (c >> 2), o = (c & 3) * 16;
            cpa16(sb + DS_OFF + r * 64 + o, dgbase + (size_t)r * 2048 + kt * 64 + o);
        }
    };

    // ---- Q fragments (register-resident)
    uint32_t Qa[8][4];
    {
        const float* qb = g_q + ((bh * 2048) + qt * 128 + w * 16) * 64;
#pragma unroll
        for (int s = 0; s < 8; s++) {
            Qa[s][0] = __float_as_uint(qb[gid * 64 + s * 8 + tig]);
            Qa[s][1] = __float_as_uint(qb[(gid + 8) * 64 + s * 8 + tig]);
            Qa[s][2] = __float_as_uint(qb[gid * 64 + s * 8 + tig + 4]);
            Qa[s][3] = __float_as_uint(qb[(gid + 8) * 64 + s * 8 + tig + 4]);
        }
    }
    if (tid < 32) btc[tid] = bias_table[tid * 12 + h];

    // ---- per-lane LDSM address bases (row pitch 272 B)
    const uint32_t rowB = (l & 7) + ((l >> 4) & 1) * 8;
    const uint32_t colB = ((l >> 3) & 1) * 4;
    const uint32_t kvoff = (rowB * 68 + colB) * 4;
    const uint32_t prowA = (l & 7) + ((l >> 3) & 1) * 8;
    const uint32_t pcolA = ((l >> 4) & 1) * 4;
    const uint32_t pbase = sb + PS_OFF + ((w * 16 + prowA) * 68 + pcolA) * 4;

    float O[8][4];
#pragma unroll
    for (int n = 0; n < 8; n++)
#pragma unroll
        for (int j = 0; j < 4; j++) O[n][j] = 0.f;
    float lsum0 = 0.f, lsum1 = 0.f;

    stage_kv(0, 0);
    stage_dm(0);
    CP_COMMIT();

    for (int kt = 0; kt < 32; kt++) {
        CP_WAIT0();
        __syncthreads();
        if (kt < 31) { stage_kv(kt + 1, (kt + 1) & 1); CP_COMMIT(); }

        const uint32_t stg = sb + (kt & 1) * STG_SZ;
        const uint32_t kbase = stg + kvoff;
        const uint32_t vbase = stg + VT_REL + kvoff;
        const float* mng = (const float*)(smem + (kt & 1) * STG_SZ + MNG_REL);

        // ---- S = Q @ K^T
        float S[8][4];
#pragma unroll
        for (int n = 0; n < 8; n++)
#pragma unroll
            for (int j = 0; j < 4; j++) S[n][j] = 0.f;
#pragma unroll
        for (int s = 0; s < 8; s++) {
            uint32_t Bf[4][4];
#pragma unroll
            for (int p = 0; p < 4; p++) ldsm4(Bf[p], kbase + p * 4352 + s * 32);
#pragma unroll
            for (int p = 0; p < 4; p++) {
                mma8(S[2 * p], Qa[s], &Bf[p][0]);
                mma8(S[2 * p + 1], Qa[s], &Bf[p][2]);
            }
        }

        // ---- bias + mask + exp -> Ps
        const unsigned char* d0p = Ds + (w * 16 + gid) * 64;
        const unsigned char* d1p = Ds + (w * 16 + gid + 8) * 64;
        const int prow = w * 16 + gid;
#pragma unroll
        for (int n = 0; n < 8; n++) {
            const int c0 = n * 8 + tig * 2;
            const float mg0 = mng[c0], mg1 = mng[c0 + 1];
            float p00 = to_tf32(__expf(S[n][0] + btc[d0p[c0]] + mg0));
            float p01 = to_tf32(__expf(S[n][1] + btc[d0p[c0 + 1]] + mg1));
            float p10 = to_tf32(__expf(S[n][2] + btc[d1p[c0]] + mg0));
            float p11 = to_tf32(__expf(S[n][3] + btc[d1p[c0 + 1]] + mg1));
            lsum0 += p00 + p01;
            lsum1 += p10 + p11;
            *(float2*)&Ps[prow * 68 + c0] = make_float2(p00, p01);
            *(float2*)&Ps[(prow + 8) * 68 + c0] = make_float2(p10, p11);
        }
        __syncwarp();
        if (kt < 31) { stage_dm(kt + 1); CP_COMMIT(); }

        // ---- O += P @ V
#pragma unroll
        for (int kk = 0; kk < 8; kk++) {
            uint32_t Pa[4];
            ldsm4(Pa, pbase + kk * 32);
            uint32_t Vf[4][4];
#pragma unroll
            for (int p = 0; p < 4; p++) ldsm4(Vf[p], vbase + p * 4352 + kk * 32);
#pragma unroll
            for (int p = 0; p < 4; p++) {
                mma8(O[2 * p], Pa, &Vf[p][0]);
                mma8(O[2 * p + 1], Pa, &Vf[p][2]);
            }
        }
    }

    // ---- epilogue: quad-reduce, normalize, tf32-round (proj A input), write
    lsum0 += __shfl_xor_sync(0xffffffffu, lsum0, 1);
    lsum0 += __shfl_xor_sync(0xffffffffu, lsum0, 2);
    lsum1 += __shfl_xor_sync(0xffffffffu, lsum1, 1);
    lsum1 += __shfl_xor_sync(0xffffffffu, lsum1, 2);
    const float inv0 = 1.0f / lsum0, inv1 = 1.0f / lsum1;
    float* dst = g_ao + ((size_t)b * 2048 + qt * 128 + w * 16) * 768 + h * 64;
#pragma unroll
    for (int n = 0; n < 8; n++) {
        const int c0 = n * 8 + tig * 2;
        *(float2*)&dst[gid * 768 + c0] =
            make_float2(to_tf32(O[n][0] * inv0), to_tf32(O[n][1] * inv0));
        *(float2*)&dst[(gid + 8) * 768 + c0] =
            make_float2(to_tf32(O[n][2] * inv1), to_tf32(O[n][3] * inv1));
    }
}

// =============================================================================
extern "C" void kernel_launch(void* const* d_in, const int* in_sizes, int n_in,
                              void* d_out, int out_size) {
    const float* x         = (const float*)d_in[0];
    const int* dist        = (const int*)d_in[1];
    const unsigned int* mk = (const unsigned int*)d_in[2];
    const float* qkv_w     = (const float*)d_in[3];
    const float* qkv_b     = (const float*)d_in[4];
    const float* out_w     = (const float*)d_in[5];
    const float* out_b     = (const float*)d_in[6];
    const float* bt        = (const float*)d_in[7];
    float* out             = (float*)d_out;

    mask_prep<<<1, 256>>>(mk);
    dist_pack<<<4096, 256>>>(dist);
    round_tf32_k<<<3072, 256>>>(x, 2 * 2048 * 768, 0);
    round_tf32_k<<<1728, 256>>>(qkv_w, 768 * 2304, 1);
    round_tf32_k<<<576, 256>>>(out_w, 768 * 768, 2);

    dim3 g1(18, 32);
    gemm_tc<<<g1, 256>>>(nullptr, nullptr, qkv_b, nullptr, 2304, 0);

    dim3 gt(32, 24);
    v_transpose<<<gt, 256>>>();

    cudaFuncSetAttribute(attn_mma, cudaFuncAttributeMaxDynamicSharedMemorySize, ATTN_SMEM);
    dim3 g2(16, 12, 2);
    attn_mma<<<g2, 256, ATTN_SMEM>>>(bt);

    dim3 g3(6, 32);
    gemm_tc<<<g3, 256>>>(nullptr, nullptr, out_b, out, 768, 1);
}

// round 13
// speedup vs baseline: 1.0282x; 1.0282x over previous
#include <cuda_runtime.h>
#include <cstdint>

// ---------------- scratch (allocation-free rule: __device__ globals) ----------
// g_q/g_k/g_v : [B,H,N,64] (tf32-rounded; q pre-scaled by 0.125)
// g_vt : [B,H,64,N]   g_ao : [B,N,768] (tf32-rounded)
// g_xr/g_wr/g_w2r : rna-rounded copies of x / qkv_w / out_w
// g_part/g_lsum : split-K attention partials (R13)
__device__ float g_q[2 * 12 * 2048 * 64];
__device__ float g_k[2 * 12 * 2048 * 64];
__device__ float g_v[2 * 12 * 2048 * 64];
__device__ float g_vt[2 * 12 * 64 * 2048];
__device__ float g_ao[2 * 2048 * 768];
__device__ float g_xr[2 * 2048 * 768];
__device__ float g_wr[768 * 2304];
__device__ float g_w2r[768 * 768];
__device__ float g_part[2 * 2 * 12 * 2048 * 64];    // [split][bh*2048+n][64]
__device__ float g_lsum[2 * 2 * 12 * 2048];         // [split][bh*2048+n]
__device__ float g_mneg[2 * 2048];                  // 0 or -1e30 per key
__device__ unsigned char g_dist8[2 * 2048 * 2048];  // clipped dist, 1 byte

__device__ __forceinline__ float to_tf32(float x) {
    float r;
    asm("cvt.rna.tf32.f32 %0, %1;" : "=f"(r) : "f"(x));
    return r;
}
__device__ __forceinline__ void mma8(float* c, const uint32_t* a, const uint32_t* b) {
    asm("mma.sync.aligned.m16n8k8.row.col.f32.tf32.tf32.f32 "
        "{%0,%1,%2,%3},{%4,%5,%6,%7},{%8,%9},{%0,%1,%2,%3};"
        : "+f"(c[0]), "+f"(c[1]), "+f"(c[2]), "+f"(c[3])
        : "r"(a[0]), "r"(a[1]), "r"(a[2]), "r"(a[3]), "r"(b[0]), "r"(b[1]));
}
__device__ __forceinline__ uint32_t smem_u32(const void* p) {
    uint32_t a;
    asm("{ .reg .u64 t; cvta.to.shared.u64 t, %1; cvt.u32.u64 %0, t; }" : "=r"(a) : "l"(p));
    return a;
}
__device__ __forceinline__ void ldsm4(uint32_t* r, uint32_t addr) {
    asm volatile("ldmatrix.sync.aligned.m8n8.x4.shared.b16 {%0,%1,%2,%3}, [%4];"
                 : "=r"(r[0]), "=r"(r[1]), "=r"(r[2]), "=r"(r[3]) : "r"(addr));
}
__device__ __forceinline__ void cpa16(uint32_t saddr, const void* g) {
    asm volatile("cp.async.cg.shared.global [%0], [%1], 16;" :: "r"(saddr), "l"(g));
}
#define CP_COMMIT() asm volatile("cp.async.commit_group;" ::: "memory")
#define CP_WAIT0()  asm volatile("cp.async.wait_group 0;" ::: "memory")

// =============================================================================
// Kernel 0a: mask dtype sniffer + conversion (validated R3)
// =============================================================================
__global__ void mask_prep(const unsigned int* __restrict__ mw) {
    const int tid = threadIdx.x;
    int ok_int = 1, ok_flt = 1;
    for (int i = tid; i < 1024; i += 256) {
        unsigned int v = mw[i];
        if (v != 0u && v != 1u) ok_int = 0;
        if (v != 0u && v != 0x3F800000u) ok_flt = 0;
    }
    ok_int = __syncthreads_and(ok_int);
    ok_flt = __syncthreads_and(ok_flt);
    if (ok_int) {
        const int* m = (const int*)mw;
        for (int i = tid; i < 4096; i += 256) g_mneg[i] = m[i] ? -1e30f : 0.0f;
    } else if (ok_flt) {
        const float* m = (const float*)mw;
        for (int i = tid; i < 4096; i += 256) g_mneg[i] = (m[i] != 0.0f) ? -1e30f : 0.0f;
    } else {
        const unsigned char* m = (const unsigned char*)mw;
        for (int i = tid; i < 4096; i += 256) g_mneg[i] = m[i] ? -1e30f : 0.0f;
    }
}

// =============================================================================
// Kernel 0b: pack dist int32 -> clipped uint8 (validated R6)
// =============================================================================
__global__ void dist_pack(const int* __restrict__ dist) {
    size_t i = ((size_t)blockIdx.x * 256 + threadIdx.x) * 8;
    int4 a = *(const int4*)(dist + i);
    int4 b = *(const int4*)(dist + i + 4);
    unsigned c0 = (unsigned)min(max(a.x, 0), 31) | ((unsigned)min(max(a.y, 0), 31) << 8) |
                  ((unsigned)min(max(a.z, 0), 31) << 16) | ((unsigned)min(max(a.w, 0), 31) << 24);
    unsigned c1 = (unsigned)min(max(b.x, 0), 31) | ((unsigned)min(max(b.y, 0), 31) << 8) |
                  ((unsigned)min(max(b.z, 0), 31) << 16) | ((unsigned)min(max(b.w, 0), 31) << 24);
    *(uint2*)(g_dist8 + i) = make_uint2(c0, c1);
}

// =============================================================================
// Kernel 0c (R13): all three tf32 roundings in ONE launch (block-range dispatch).
// Exact grids: x 3072 blocks, qkv_w 1728, out_w 576 -> 5376 total, no bounds waste.
// =============================================================================
__global__ void round_all(const float* __restrict__ x,
                          const float* __restrict__ w1,
                          const float* __restrict__ w2) {
    const int bid = blockIdx.x;
    const float* src;
    float* dst;
    int i;
    if (bid < 3072)      { src = x;  dst = g_xr;  i = (bid * 256 + threadIdx.x) * 4; }
    else if (bid < 4800) { src = w1; dst = g_wr;  i = ((bid - 3072) * 256 + threadIdx.x) * 4; }
    else                 { src = w2; dst = g_w2r; i = ((bid - 4800) * 256 + threadIdx.x) * 4; }
    float4 v = *(const float4*)(src + i);
    *(float4*)(dst + i) =
        make_float4(to_tf32(v.x), to_tf32(v.y), to_tf32(v.z), to_tf32(v.w));
}

// =============================================================================
// Kernel 1: tf32 tensor-core GEMM v2 (validated R11/R12)
// =============================================================================
__global__ __launch_bounds__(256) void gemm_tc(const float* __restrict__ A,
                                               const float* __restrict__ W,
                                               const float* __restrict__ Bv,
                                               float* __restrict__ outp,
                                               int N, int mode) {
    if (mode == 0) { A = g_xr; W = g_wr; }   // device-side symbols (R7 lesson)
    else           { A = g_ao; W = g_w2r; }
    __shared__ float As[2][128][20];
    __shared__ float Bs[2][16][136];
    const int tid = threadIdx.x, w = tid >> 5, l = tid & 31;
    const int gid = l >> 2, tig = l & 3;
    const int wm = w >> 2, wn = w & 3;
    const int bM = blockIdx.y * 128, bN = blockIdx.x * 128;
    const uint32_t sb_a = smem_u32(&As[0][0][0]);
    const uint32_t sb_b = smem_u32(&Bs[0][0][0]);

    auto stage = [&](int k0, int buf) {
#pragma unroll
        for (int j = 0; j < 2; j++) {
            int c = tid + j * 256, r = c >> 2, o = c & 3;
            cpa16(sb_a + buf * 10240 + r * 80 + o * 16,
                  A + (size_t)(bM + r) * 768 + k0 + o * 4);
        }
#pragma unroll
        for (int j = 0; j < 2; j++) {
            int c = tid + j * 256, r = c >> 5, o = c & 31;
            cpa16(sb_b + buf * 8704 + r * 544 + o * 16,
                  W + (size_t)(k0 + r) * N + bN + o * 4);
        }
    };

    float acc[4][4][4];
#pragma unroll
    for (int mi = 0; mi < 4; mi++)
#pragma unroll
        for (int ni = 0; ni < 4; ni++)
#pragma unroll
            for (int j = 0; j < 4; j++) acc[mi][ni][j] = 0.f;

    const uint32_t prowA = (l & 7) + ((l >> 3) & 1) * 8;
    const uint32_t pcolA = ((l >> 4) & 1) * 4;

    stage(0, 0);
    CP_COMMIT();

    for (int ks = 0; ks < 48; ks++) {
        CP_WAIT0();
        __syncthreads();
        if (ks < 47) { stage((ks + 1) * 16, (ks + 1) & 1); CP_COMMIT(); }
        const int buf = ks & 1;
        const uint32_t abase = sb_a + buf * 10240;

#pragma unroll
        for (int kk = 0; kk < 2; kk++) {
            const int kb = kk * 8;
            uint32_t Af[4][4], Bf[4][2];
#pragma unroll
            for (int mi = 0; mi < 4; mi++) {
                const int m0 = wm * 64 + mi * 16;
                ldsm4(Af[mi], abase + (m0 + prowA) * 80 + (kb + pcolA) * 4);
            }
#pragma unroll
            for (int ni = 0; ni < 4; ni++) {
                const int n0 = wn * 32 + ni * 8 + gid;
                Bf[ni][0] = __float_as_uint(Bs[buf][kb + tig][n0]);
                Bf[ni][1] = __float_as_uint(Bs[buf][kb + tig + 4][n0]);
            }
#pragma unroll
            for (int mi = 0; mi < 4; mi++)
#pragma unroll
                for (int ni = 0; ni < 4; ni++) mma8(acc[mi][ni], Af[mi], Bf[ni]);
        }
    }

#pragma unroll
    for (int ni = 0; ni < 4; ni++) {
        const int col0 = bN + wn * 32 + ni * 8 + tig * 2;
        const float b0 = Bv[col0], b1 = Bv[col0 + 1];
        if (mode == 0) {
            const int which = col0 / 768;
            const int rem = col0 % 768;
            const int hh = rem / 64, hd0 = rem % 64;
            float* dst = (which == 0) ? g_q : (which == 1 ? g_k : g_v);
            const float qs = (which == 0) ? 0.125f : 1.0f;
#pragma unroll
            for (int mi = 0; mi < 4; mi++) {
                const int row = bM + wm * 64 + mi * 16 + gid;
                const int bidx = row >> 11, n = row & 2047;
                float* p = dst + ((((size_t)bidx * 12 + hh) * 2048 + n) * 64 + hd0);
                *(float2*)p = make_float2(to_tf32((acc[mi][ni][0] + b0) * qs),
                                          to_tf32((acc[mi][ni][1] + b1) * qs));
                const int row2 = row + 8;
                const int bidx2 = row2 >> 11, n2 = row2 & 2047;
                float* p2 = dst + ((((size_t)bidx2 * 12 + hh) * 2048 + n2) * 64 + hd0);
                *(float2*)p2 = make_float2(to_tf32((acc[mi][ni][2] + b0) * qs),
                                           to_tf32((acc[mi][ni][3] + b1) * qs));
            }
        } else {
#pragma unroll
            for (int mi = 0; mi < 4; mi++) {
                const int row = bM + wm * 64 + mi * 16 + gid;
                *(float2*)(outp + (size_t)row * 768 + col0) =
                    make_float2(acc[mi][ni][0] + b0, acc[mi][ni][1] + b1);
                *(float2*)(outp + (size_t)(row + 8) * 768 + col0) =
                    make_float2(acc[mi][ni][2] + b0, acc[mi][ni][3] + b1);
            }
        }
    }
}

// =============================================================================
// Kernel 1b: transpose V -> g_vt [B,H,64,N] (validated R9)
// =============================================================================
__global__ __launch_bounds__(256) void v_transpose() {
    __shared__ float sm[64 * 65];
    const int n0 = blockIdx.x * 64;
    const int bh = blockIdx.y;
    const float* src = g_v + ((size_t)bh * 2048 + n0) * 64;
    for (int v = threadIdx.x; v < 1024; v += 256) {
        int i = v >> 4, d4 = (v & 15) << 2;
        float4 t = *(const float4*)(src + i * 64 + d4);
        sm[(d4 + 0) * 65 + i] = t.x; sm[(d4 + 1) * 65 + i] = t.y;
        sm[(d4 + 2) * 65 + i] = t.z; sm[(d4 + 3) * 65 + i] = t.w;
    }
    __syncthreads();
    float* dst = g_vt + (size_t)bh * 64 * 2048 + n0;
    for (int v = threadIdx.x; v < 1024; v += 256) {
        int d = v >> 4, j4 = (v & 15) << 2;
        *(float4*)(dst + (size_t)d * 2048 + j4) =
            make_float4(sm[d * 65 + j4], sm[d * 65 + j4 + 1],
                        sm[d * 65 + j4 + 2], sm[d * 65 + j4 + 3]);
    }
}

// =============================================================================
// Kernel 2: tf32 flash attention — split-K edition (R13).
// blockIdx.z = b*2 + split; each CTA sweeps 16 key tiles and writes UNNORMALIZED
// partial O + partial lsum. Plain-exp softmax (no running max) makes partials
// additive: O = (O1+O2)/(l1+l2), done in combine_k.
// =============================================================================
static constexpr int VT_REL = 17408;
static constexpr int MNG_REL = 34816;
static constexpr int STG_SZ = 35072;
static constexpr int DS_OFF = 70144;
static constexpr int PS_OFF = 78336;
static constexpr int BT_OFF = 113152;
static constexpr int ATTN_SMEM = 113280;      // <= 114688 -> 2 CTAs/SM

__global__ __launch_bounds__(256, 2) void attn_mma(const float* __restrict__ bias_table) {
    extern __shared__ char smem[];
    const uint32_t sb = smem_u32(smem);
    unsigned char* Ds = (unsigned char*)(smem + DS_OFF);
    float* Ps = (float*)(smem + PS_OFF);
    float* btc = (float*)(smem + BT_OFF);

    const int tid = threadIdx.x, w = tid >> 5, l = tid & 31;
    const int gid = l >> 2, tig = l & 3;
    const int qt = blockIdx.x, h = blockIdx.y;
    const int b = blockIdx.z >> 1, sp = blockIdx.z & 1;
    const int kt0 = sp * 16;                     // this CTA's 16 key tiles
    const size_t bh = (size_t)b * 12 + h;

    const char* kgbase = (const char*)(g_k + (bh * 2048) * 64);
    const char* vgbase = (const char*)(g_vt + bh * 131072);
    const unsigned char* dgbase = g_dist8 + (size_t)(b * 2048 + qt * 128) * 2048;

    auto stage_kv = [&](int kt, int buf) {
        const uint32_t base = sb + buf * STG_SZ;
#pragma unroll
        for (int j = 0; j < 4; j++) {
            int c = tid + j * 256, r = c >> 4, o = (c & 15) * 16;
            cpa16(base + r * 272 + o, kgbase + ((size_t)(kt * 64 + r) * 256) + o);
        }
#pragma unroll
        for (int j = 0; j < 4; j++) {
            int c = tid + j * 256, r = c >> 4, o = (c & 15) * 16;
            cpa16(base + VT_REL + r * 272 + o, vgbase + ((size_t)r * 8192) + kt * 256 + o);
        }
        if (tid < 16) cpa16(base + MNG_REL + tid * 16, g_mneg + b * 2048 + kt * 64 + tid * 4);
    };
    auto stage_dm = [&](int kt) {
#pragma unroll
        for (int j = 0; j < 2; j++) {
            int c = l + j * 32, r = w * 16 + (c >> 2), o = (c & 3) * 16;
            cpa16(sb + DS_OFF + r * 64 + o, dgbase + (size_t)r * 2048 + kt * 64 + o);
        }
    };

    // ---- Q fragments (register-resident)
    uint32_t Qa[8][4];
    {
        const float* qb = g_q + ((bh * 2048) + qt * 128 + w * 16) * 64;
#pragma unroll
        for (int s = 0; s < 8; s++) {
            Qa[s][0] = __float_as_uint(qb[gid * 64 + s * 8 + tig]);
            Qa[s][1] = __float_as_uint(qb[(gid + 8) * 64 + s * 8 + tig]);
            Qa[s][2] = __float_as_uint(qb[gid * 64 + s * 8 + tig + 4]);
            Qa[s][3] = __float_as_uint(qb[(gid + 8) * 64 + s * 8 + tig + 4]);
        }
    }
    if (tid < 32) btc[tid] = bias_table[tid * 12 + h];

    const uint32_t rowB = (l & 7) + ((l >> 4) & 1) * 8;
    const uint32_t colB = ((l >> 3) & 1) * 4;
    const uint32_t kvoff = (rowB * 68 + colB) * 4;
    const uint32_t prowA = (l & 7) + ((l >> 3) & 1) * 8;
    const uint32_t pcolA = ((l >> 4) & 1) * 4;
    const uint32_t pbase = sb + PS_OFF + ((w * 16 + prowA) * 68 + pcolA) * 4;

    float O[8][4];
#pragma unroll
    for (int n = 0; n < 8; n++)
#pragma unroll
        for (int j = 0; j < 4; j++) O[n][j] = 0.f;
    float lsum0 = 0.f, lsum1 = 0.f;

    stage_kv(kt0, 0);    // kt0 is even -> buf parity kt&1 starts at 0 for both splits
    stage_dm(kt0);
    CP_COMMIT();

    for (int kt = kt0; kt < kt0 + 16; kt++) {
        CP_WAIT0();
        __syncthreads();
        if (kt < kt0 + 15) { stage_kv(kt + 1, (kt + 1) & 1); CP_COMMIT(); }

        const uint32_t stg = sb + (kt & 1) * STG_SZ;
        const uint32_t kbase = stg + kvoff;
        const uint32_t vbase = stg + VT_REL + kvoff;
        const float* mng = (const float*)(smem + (kt & 1) * STG_SZ + MNG_REL);

        // ---- S = Q @ K^T
        float S[8][4];
#pragma unroll
        for (int n = 0; n < 8; n++)
#pragma unroll
            for (int j = 0; j < 4; j++) S[n][j] = 0.f;
#pragma unroll
        for (int s = 0; s < 8; s++) {
            uint32_t Bf[4][4];
#pragma unroll
            for (int p = 0; p < 4; p++) ldsm4(Bf[p], kbase + p * 4352 + s * 32);
#pragma unroll
            for (int p = 0; p < 4; p++) {
                mma8(S[2 * p], Qa[s], &Bf[p][0]);
                mma8(S[2 * p + 1], Qa[s], &Bf[p][2]);
            }
        }

        // ---- bias + mask + exp -> Ps
        const unsigned char* d0p = Ds + (w * 16 + gid) * 64;
        const unsigned char* d1p = Ds + (w * 16 + gid + 8) * 64;
        const int prow = w * 16 + gid;
#pragma unroll
        for (int n = 0; n < 8; n++) {
            const int c0 = n * 8 + tig * 2;
            const float mg0 = mng[c0], mg1 = mng[c0 + 1];
            float p00 = to_tf32(__expf(S[n][0] + btc[d0p[c0]] + mg0));
            float p01 = to_tf32(__expf(S[n][1] + btc[d0p[c0 + 1]] + mg1));
            float p10 = to_tf32(__expf(S[n][2] + btc[d1p[c0]] + mg0));
            float p11 = to_tf32(__expf(S[n][3] + btc[d1p[c0 + 1]] + mg1));
            lsum0 += p00 + p01;
            lsum1 += p10 + p11;
            *(float2*)&Ps[prow * 68 + c0] = make_float2(p00, p01);
            *(float2*)&Ps[(prow + 8) * 68 + c0] = make_float2(p10, p11);
        }
        __syncwarp();
        if (kt < kt0 + 15) { stage_dm(kt + 1); CP_COMMIT(); }

        // ---- O += P @ V
#pragma unroll
        for (int kk = 0; kk < 8; kk++) {
            uint32_t Pa[4];
            ldsm4(Pa, pbase + kk * 32);
            uint32_t Vf[4][4];
#pragma unroll
            for (int p = 0; p < 4; p++) ldsm4(Vf[p], vbase + p * 4352 + kk * 32);
#pragma unroll
            for (int p = 0; p < 4; p++) {
                mma8(O[2 * p], Pa, &Vf[p][0]);
                mma8(O[2 * p + 1], Pa, &Vf[p][2]);
            }
        }
    }

    // ---- epilogue: quad-reduce lsum, write UNNORMALIZED partials
    lsum0 += __shfl_xor_sync(0xffffffffu, lsum0, 1);
    lsum0 += __shfl_xor_sync(0xffffffffu, lsum0, 2);
    lsum1 += __shfl_xor_sync(0xffffffffu, lsum1, 1);
    lsum1 += __shfl_xor_sync(0xffffffffu, lsum1, 2);
    const size_t rbase = bh * 2048 + qt * 128 + w * 16;
    float* dst = g_part + (size_t)sp * 3145728 + rbase * 64;
#pragma unroll
    for (int n = 0; n < 8; n++) {
        const int c0 = n * 8 + tig * 2;
        *(float2*)&dst[gid * 64 + c0] = make_float2(O[n][0], O[n][1]);
        *(float2*)&dst[(gid + 8) * 64 + c0] = make_float2(O[n][2], O[n][3]);
    }
    if (tig == 0) {
        g_lsum[sp * 49152 + rbase + gid] = lsum0;
        g_lsum[sp * 49152 + rbase + gid + 8] = lsum1;
    }
}

// =============================================================================
// Kernel 2b (R13): combine split-K partials -> g_ao = tf32((O1+O2)/(l1+l2)).
// i enumerates [b][n][768]; exact grid 3072 x 256 x 4 floats.
// =============================================================================
__global__ void combine_k() {
    const int i = (blockIdx.x * 256 + threadIdx.x) * 4;
    const int b = i / (2048 * 768);
    const int rem = i - b * 2048 * 768;
    const int n = rem / 768;
    const int c = rem - n * 768;
    const int h = c >> 6, hd = c & 63;
    const size_t row = ((size_t)(b * 12 + h)) * 2048 + n;
    const size_t p = row * 64 + hd;
    float4 o1 = *(const float4*)(g_part + p);
    float4 o2 = *(const float4*)(g_part + 3145728 + p);
    const float inv = 1.0f / (g_lsum[row] + g_lsum[49152 + row]);
    *(float4*)(g_ao + i) = make_float4(to_tf32((o1.x + o2.x) * inv),
                                       to_tf32((o1.y + o2.y) * inv),
                                       to_tf32((o1.z + o2.z) * inv),
                                       to_tf32((o1.w + o2.w) * inv));
}

// =============================================================================
extern "C" void kernel_launch(void* const* d_in, const int* in_sizes, int n_in,
                              void* d_out, int out_size) {
    const float* x         = (const float*)d_in[0];
    const int* dist        = (const int*)d_in[1];
    const unsigned int* mk = (const unsigned int*)d_in[2];
    const float* qkv_w     = (const float*)d_in[3];
    const float* qkv_b     = (const float*)d_in[4];
    const float* out_w     = (const float*)d_in[5];
    const float* out_b     = (const float*)d_in[6];
    const float* bt        = (const float*)d_in[7];
    float* out             = (float*)d_out;

    mask_prep<<<1, 256>>>(mk);
    dist_pack<<<4096, 256>>>(dist);
    round_all<<<5376, 256>>>(x, qkv_w, out_w);

    dim3 g1(18, 32);
    gemm_tc<<<g1, 256>>>(nullptr, nullptr, qkv_b, nullptr, 2304, 0);

    dim3 gt(32, 24);
    v_transpose<<<gt, 256>>>();

    cudaFuncSetAttribute(attn_mma, cudaFuncAttributeMaxDynamicSharedMemorySize, ATTN_SMEM);
    dim3 g2(16, 12, 4);
    attn_mma<<<g2, 256, ATTN_SMEM>>>(bt);

    combine_k<<<3072, 256>>>();

    dim3 g3(6, 32);
    gemm_tc<<<g3, 256>>>(nullptr, nullptr, out_b, out, 768, 1);
}

// round 14
// speedup vs baseline: 1.3348x; 1.2983x over previous
#include <cuda_runtime.h>
#include <cuda_fp16.h>
#include <cstdint>

// ---------------- scratch (allocation-free rule: __device__ globals) ----------
// g_q/g_k/g_v : half [B,H,N,64] (q pre-scaled 0.125)  g_vt : half [B,H,64,N]
// g_ao : [B,N,768] float (tf32-rounded)  g_xr/g_wr/g_w2r : rounded GEMM inputs
__device__ __half g_q[2 * 12 * 2048 * 64];
__device__ __half g_k[2 * 12 * 2048 * 64];
__device__ __half g_v[2 * 12 * 2048 * 64];
__device__ __half g_vt[2 * 12 * 64 * 2048];
__device__ float g_ao[2 * 2048 * 768];
__device__ float g_xr[2 * 2048 * 768];
__device__ float g_wr[768 * 2304];
__device__ float g_w2r[768 * 768];
__device__ float g_part[2 * 2 * 12 * 2048 * 64];    // [split][bh*2048+n][64]
__device__ float g_lsum[2 * 2 * 12 * 2048];         // [split][bh*2048+n]
__device__ float g_mneg[2 * 2048];                  // 0 or -1e30 per key
__device__ unsigned char g_dist8[2 * 2048 * 2048];  // clipped dist, 1 byte

__device__ __forceinline__ float to_tf32(float x) {
    float r;
    asm("cvt.rna.tf32.f32 %0, %1;" : "=f"(r) : "f"(x));
    return r;
}
// tf32 k8 mma (GEMMs, validated R8-R13)
__device__ __forceinline__ void mma8(float* c, const uint32_t* a, const uint32_t* b) {
    asm("mma.sync.aligned.m16n8k8.row.col.f32.tf32.tf32.f32 "
        "{%0,%1,%2,%3},{%4,%5,%6,%7},{%8,%9},{%0,%1,%2,%3};"
        : "+f"(c[0]), "+f"(c[1]), "+f"(c[2]), "+f"(c[3])
        : "r"(a[0]), "r"(a[1]), "r"(a[2]), "r"(a[3]), "r"(b[0]), "r"(b[1]));
}
// fp16 k16 mma (attention, R14): same mantissa as tf32, 2x rate
__device__ __forceinline__ void mma16(float* c, const uint32_t* a, const uint32_t* b) {
    asm("mma.sync.aligned.m16n8k16.row.col.f32.f16.f16.f32 "
        "{%0,%1,%2,%3},{%4,%5,%6,%7},{%8,%9},{%0,%1,%2,%3};"
        : "+f"(c[0]), "+f"(c[1]), "+f"(c[2]), "+f"(c[3])
        : "r"(a[0]), "r"(a[1]), "r"(a[2]), "r"(a[3]), "r"(b[0]), "r"(b[1]));
}
__device__ __forceinline__ uint32_t smem_u32(const void* p) {
    uint32_t a;
    asm("{ .reg .u64 t; cvta.to.shared.u64 t, %1; cvt.u32.u64 %0, t; }" : "=r"(a) : "l"(p));
    return a;
}
__device__ __forceinline__ void ldsm4(uint32_t* r, uint32_t addr) {
    asm volatile("ldmatrix.sync.aligned.m8n8.x4.shared.b16 {%0,%1,%2,%3}, [%4];"
                 : "=r"(r[0]), "=r"(r[1]), "=r"(r[2]), "=r"(r[3]) : "r"(addr));
}
__device__ __forceinline__ void cpa16(uint32_t saddr, const void* g) {
    asm volatile("cp.async.cg.shared.global [%0], [%1], 16;" :: "r"(saddr), "l"(g));
}
#define CP_COMMIT() asm volatile("cp.async.commit_group;" ::: "memory")
#define CP_WAIT0()  asm volatile("cp.async.wait_group 0;" ::: "memory")

// =============================================================================
// Kernel 0a: mask dtype sniffer + conversion (validated R3)
// =============================================================================
__global__ void mask_prep(const unsigned int* __restrict__ mw) {
    const int tid = threadIdx.x;
    int ok_int = 1, ok_flt = 1;
    for (int i = tid; i < 1024; i += 256) {
        unsigned int v = mw[i];
        if (v != 0u && v != 1u) ok_int = 0;
        if (v != 0u && v != 0x3F800000u) ok_flt = 0;
    }
    ok_int = __syncthreads_and(ok_int);
    ok_flt = __syncthreads_and(ok_flt);
    if (ok_int) {
        const int* m = (const int*)mw;
        for (int i = tid; i < 4096; i += 256) g_mneg[i] = m[i] ? -1e30f : 0.0f;
    } else if (ok_flt) {
        const float* m = (const float*)mw;
        for (int i = tid; i < 4096; i += 256) g_mneg[i] = (m[i] != 0.0f) ? -1e30f : 0.0f;
    } else {
        const unsigned char* m = (const unsigned char*)mw;
        for (int i = tid; i < 4096; i += 256) g_mneg[i] = m[i] ? -1e30f : 0.0f;
    }
}

// =============================================================================
// Kernel 0b: pack dist int32 -> clipped uint8 (validated R6)
// =============================================================================
__global__ void dist_pack(const int* __restrict__ dist) {
    size_t i = ((size_t)blockIdx.x * 256 + threadIdx.x) * 8;
    int4 a = *(const int4*)(dist + i);
    int4 b = *(const int4*)(dist + i + 4);
    unsigned c0 = (unsigned)min(max(a.x, 0), 31) | ((unsigned)min(max(a.y, 0), 31) << 8) |
                  ((unsigned)min(max(a.z, 0), 31) << 16) | ((unsigned)min(max(a.w, 0), 31) << 24);
    unsigned c1 = (unsigned)min(max(b.x, 0), 31) | ((unsigned)min(max(b.y, 0), 31) << 8) |
                  ((unsigned)min(max(b.z, 0), 31) << 16) | ((unsigned)min(max(b.w, 0), 31) << 24);
    *(uint2*)(g_dist8 + i) = make_uint2(c0, c1);
}

// =============================================================================
// Kernel 0c: all three tf32 roundings in one launch (validated R13)
// =============================================================================
__global__ void round_all(const float* __restrict__ x,
                          const float* __restrict__ w1,
                          const float* __restrict__ w2) {
    const int bid = blockIdx.x;
    const float* src;
    float* dst;
    int i;
    if (bid < 3072)      { src = x;  dst = g_xr;  i = (bid * 256 + threadIdx.x) * 4; }
    else if (bid < 4800) { src = w1; dst = g_wr;  i = ((bid - 3072) * 256 + threadIdx.x) * 4; }
    else                 { src = w2; dst = g_w2r; i = ((bid - 4800) * 256 + threadIdx.x) * 4; }
    float4 v = *(const float4*)(src + i);
    *(float4*)(dst + i) =
        make_float4(to_tf32(v.x), to_tf32(v.y), to_tf32(v.z), to_tf32(v.w));
}

// =============================================================================
// Kernel 1: tf32 tensor-core GEMM (validated R11-R13).
// mode 0 epilogue now emits HALF q/k/v (R14).
// =============================================================================
__global__ __launch_bounds__(256) void gemm_tc(const float* __restrict__ A,
                                               const float* __restrict__ W,
                                               const float* __restrict__ Bv,
                                               float* __restrict__ outp,
                                               int N, int mode) {
    if (mode == 0) { A = g_xr; W = g_wr; }   // device-side symbols (R7 lesson)
    else           { A = g_ao; W = g_w2r; }
    __shared__ float As[2][128][20];
    __shared__ float Bs[2][16][136];
    const int tid = threadIdx.x, w = tid >> 5, l = tid & 31;
    const int gid = l >> 2, tig = l & 3;
    const int wm = w >> 2, wn = w & 3;
    const int bM = blockIdx.y * 128, bN = blockIdx.x * 128;
    const uint32_t sb_a = smem_u32(&As[0][0][0]);
    const uint32_t sb_b = smem_u32(&Bs[0][0][0]);

    auto stage = [&](int k0, int buf) {
#pragma unroll
        for (int j = 0; j < 2; j++) {
            int c = tid + j * 256, r = c >> 2, o = c & 3;
            cpa16(sb_a + buf * 10240 + r * 80 + o * 16,
                  A + (size_t)(bM + r) * 768 + k0 + o * 4);
        }
#pragma unroll
        for (int j = 0; j < 2; j++) {
            int c = tid + j * 256, r = c >> 5, o = c & 31;
            cpa16(sb_b + buf * 8704 + r * 544 + o * 16,
                  W + (size_t)(k0 + r) * N + bN + o * 4);
        }
    };

    float acc[4][4][4];
#pragma unroll
    for (int mi = 0; mi < 4; mi++)
#pragma unroll
        for (int ni = 0; ni < 4; ni++)
#pragma unroll
            for (int j = 0; j < 4; j++) acc[mi][ni][j] = 0.f;

    const uint32_t prowA = (l & 7) + ((l >> 3) & 1) * 8;
    const uint32_t pcolA = ((l >> 4) & 1) * 4;

    stage(0, 0);
    CP_COMMIT();

    for (int ks = 0; ks < 48; ks++) {
        CP_WAIT0();
        __syncthreads();
        if (ks < 47) { stage((ks + 1) * 16, (ks + 1) & 1); CP_COMMIT(); }
        const int buf = ks & 1;
        const uint32_t abase = sb_a + buf * 10240;

#pragma unroll
        for (int kk = 0; kk < 2; kk++) {
            const int kb = kk * 8;
            uint32_t Af[4][4], Bf[4][2];
#pragma unroll
            for (int mi = 0; mi < 4; mi++) {
                const int m0 = wm * 64 + mi * 16;
                ldsm4(Af[mi], abase + (m0 + prowA) * 80 + (kb + pcolA) * 4);
            }
#pragma unroll
            for (int ni = 0; ni < 4; ni++) {
                const int n0 = wn * 32 + ni * 8 + gid;
                Bf[ni][0] = __float_as_uint(Bs[buf][kb + tig][n0]);
                Bf[ni][1] = __float_as_uint(Bs[buf][kb + tig + 4][n0]);
            }
#pragma unroll
            for (int mi = 0; mi < 4; mi++)
#pragma unroll
                for (int ni = 0; ni < 4; ni++) mma8(acc[mi][ni], Af[mi], Bf[ni]);
        }
    }

#pragma unroll
    for (int ni = 0; ni < 4; ni++) {
        const int col0 = bN + wn * 32 + ni * 8 + tig * 2;
        const float b0 = Bv[col0], b1 = Bv[col0 + 1];
        if (mode == 0) {
            const int which = col0 / 768;
            const int rem = col0 % 768;
            const int hh = rem / 64, hd0 = rem % 64;
            __half* dst = (which == 0) ? g_q : (which == 1 ? g_k : g_v);
            const float qs = (which == 0) ? 0.125f : 1.0f;
#pragma unroll
            for (int mi = 0; mi < 4; mi++) {
                const int row = bM + wm * 64 + mi * 16 + gid;
                const int bidx = row >> 11, n = row & 2047;
                __half* p = dst + ((((size_t)bidx * 12 + hh) * 2048 + n) * 64 + hd0);
                *(__half2*)p =
                    __floats2half2_rn((acc[mi][ni][0] + b0) * qs, (acc[mi][ni][1] + b1) * qs);
                const int row2 = row + 8;
                const int bidx2 = row2 >> 11, n2 = row2 & 2047;
                __half* p2 = dst + ((((size_t)bidx2 * 12 + hh) * 2048 + n2) * 64 + hd0);
                *(__half2*)p2 =
                    __floats2half2_rn((acc[mi][ni][2] + b0) * qs, (acc[mi][ni][3] + b1) * qs);
            }
        } else {
#pragma unroll
            for (int mi = 0; mi < 4; mi++) {
                const int row = bM + wm * 64 + mi * 16 + gid;
                *(float2*)(outp + (size_t)row * 768 + col0) =
                    make_float2(acc[mi][ni][0] + b0, acc[mi][ni][1] + b1);
                *(float2*)(outp + (size_t)(row + 8) * 768 + col0) =
                    make_float2(acc[mi][ni][2] + b0, acc[mi][ni][3] + b1);
            }
        }
    }
}

// =============================================================================
// Kernel 1b: transpose V (half) -> g_vt [B,H,64,N] (R14 half rewrite)
// =============================================================================
__global__ __launch_bounds__(256) void v_transpose() {
    __shared__ __half smh[64 * 66];
    const int n0 = blockIdx.x * 64;
    const int bh = blockIdx.y;
    const __half2* s2 = (const __half2*)(g_v + ((size_t)bh * 2048 + n0) * 64);
    for (int v = threadIdx.x; v < 2048; v += 256) {
        int i = v >> 5, d2 = v & 31;
        __half2 h = s2[i * 32 + d2];
        smh[(2 * d2) * 66 + i] = __low2half(h);
        smh[(2 * d2 + 1) * 66 + i] = __high2half(h);
    }
    __syncthreads();
    __half2* d2p = (__half2*)(g_vt + (size_t)bh * 64 * 2048 + n0);
    for (int v = threadIdx.x; v < 2048; v += 256) {
        int d = v >> 5, j = v & 31;
        d2p[(size_t)d * 1024 + j] = __halves2half2(smh[d * 66 + 2 * j], smh[d * 66 + 2 * j + 1]);
    }
}

// =============================================================================
// Kernel 2: fp16 m16n8k16 flash attention, split-K (R14).
// Rows padded to 144 B (36 words = 4 mod 32: conflict-free LDSM phases).
// Per key tile: QK 4 k-steps x (4 LDSM + 8 mma); PV 4 x (5 LDSM + 8 mma).
// =============================================================================
static constexpr int VT_REL = 9216;           // Vt within stage (K = 64 x 144B)
static constexpr int MNG_REL = 18432;         // mask floats within stage
static constexpr int STG_SZ = 18688;
static constexpr int DS_OFF = 37376;          // dist [128][64] u8
static constexpr int PS_OFF = 45568;          // P half [128][72] = 18432 B
static constexpr int BT_OFF = 64000;          // 32 f32
static constexpr int ATTN_SMEM = 64128;

__global__ __launch_bounds__(256, 2) void attn_mma(const float* __restrict__ bias_table) {
    extern __shared__ char smem[];
    const uint32_t sb = smem_u32(smem);
    unsigned char* Ds = (unsigned char*)(smem + DS_OFF);
    char* Psb = smem + PS_OFF;
    float* btc = (float*)(smem + BT_OFF);

    const int tid = threadIdx.x, w = tid >> 5, l = tid & 31;
    const int gid = l >> 2, tig = l & 3;
    const int qt = blockIdx.x, h = blockIdx.y;
    const int b = blockIdx.z >> 1, sp = blockIdx.z & 1;
    const int kt0 = sp * 16;
    const size_t bh = (size_t)b * 12 + h;

    const char* kgbase = (const char*)(g_k + bh * 2048 * 64);
    const char* vgbase = (const char*)(g_vt + bh * 64 * 2048);
    const unsigned char* dgbase = g_dist8 + (size_t)(b * 2048 + qt * 128) * 2048;

    auto stage_kv = [&](int kt, int buf) {
        const uint32_t base = sb + buf * STG_SZ;
#pragma unroll
        for (int j = 0; j < 2; j++) {  // K: 64 rows x 128B
            int c = tid + j * 256, r = c >> 3, o = (c & 7) * 16;
            cpa16(base + r * 144 + o, kgbase + (size_t)(kt * 64 + r) * 128 + o);
        }
#pragma unroll
        for (int j = 0; j < 2; j++) {  // Vt: 64 d-rows x 128B slice
            int c = tid + j * 256, r = c >> 3, o = (c & 7) * 16;
            cpa16(base + VT_REL + r * 144 + o, vgbase + (size_t)r * 4096 + kt * 128 + o);
        }
        if (tid < 16) cpa16(base + MNG_REL + tid * 16, g_mneg + b * 2048 + kt * 64 + tid * 4);
    };
    auto stage_dm = [&](int kt) {  // warp-local dist rows (validated R11)
#pragma unroll
        for (int j = 0; j < 2; j++) {
            int c = l + j * 32, r = w * 16 + (c >> 2), o = (c & 3) * 16;
            cpa16(sb + DS_OFF + r * 64 + o, dgbase + (size_t)r * 2048 + kt * 64 + o);
        }
    };

    // ---- Q fragments (fp16, register-resident): a0..a3 canonical m16n8k16 map
    uint32_t Qa[4][4];
    {
        const char* qb = (const char*)(g_q + (bh * 2048 + qt * 128 + w * 16) * 64);
#pragma unroll
        for (int s = 0; s < 4; s++) {
            const int o = s * 32 + tig * 4;
            Qa[s][0] = *(const uint32_t*)(qb + gid * 128 + o);
            Qa[s][1] = *(const uint32_t*)(qb + (gid + 8) * 128 + o);
            Qa[s][2] = *(const uint32_t*)(qb + gid * 128 + o + 16);
            Qa[s][3] = *(const uint32_t*)(qb + (gid + 8) * 128 + o + 16);
        }
    }
    if (tid < 32) btc[tid] = bias_table[tid * 12 + h];

    // ---- per-lane LDSM bases (pitch 144B)
    const uint32_t rowB = (l & 7) + ((l >> 4) & 1) * 8;     // B-frag rows
    const uint32_t colB = ((l >> 3) & 1) * 16;              // 16B halves group
    const uint32_t kvoff = rowB * 144 + colB;
    const uint32_t prowA = (l & 7) + ((l >> 3) & 1) * 8;    // A-frag rows
    const uint32_t pcolA = ((l >> 4) & 1) * 16;
    const uint32_t pbase = sb + PS_OFF + (w * 16 + prowA) * 144 + pcolA;

    float O[8][4];
#pragma unroll
    for (int n = 0; n < 8; n++)
#pragma unroll
        for (int j = 0; j < 4; j++) O[n][j] = 0.f;
    float lsum0 = 0.f, lsum1 = 0.f;

    stage_kv(kt0, 0);   // kt0 even -> parity matches buf
    stage_dm(kt0);
    CP_COMMIT();

    for (int kt = kt0; kt < kt0 + 16; kt++) {
        CP_WAIT0();
        __syncthreads();
        if (kt < kt0 + 15) { stage_kv(kt + 1, (kt + 1) & 1); CP_COMMIT(); }

        const uint32_t stg = sb + (kt & 1) * STG_SZ;
        const uint32_t kbase = stg + kvoff;
        const uint32_t vbase = stg + VT_REL + kvoff;
        const float* mng = (const float*)(smem + (kt & 1) * STG_SZ + MNG_REL);

        // ---- S = Q @ K^T  (4 k16 steps; p = key-pair tile of 16)
        float S[8][4];
#pragma unroll
        for (int n = 0; n < 8; n++)
#pragma unroll
            for (int j = 0; j < 4; j++) S[n][j] = 0.f;
#pragma unroll
        for (int s = 0; s < 4; s++) {
            uint32_t Bf[4][4];
#pragma unroll
            for (int p = 0; p < 4; p++) ldsm4(Bf[p], kbase + p * 2304 + s * 32);
#pragma unroll
            for (int p = 0; p < 4; p++) {
                mma16(S[2 * p], Qa[s], &Bf[p][0]);
                mma16(S[2 * p + 1], Qa[s], &Bf[p][2]);
            }
        }

        // ---- bias + mask + exp -> Ps (half2 stores, conflict-free)
        const unsigned char* d0p = Ds + (w * 16 + gid) * 64;
        const unsigned char* d1p = Ds + (w * 16 + gid + 8) * 64;
        const int prow = w * 16 + gid;
#pragma unroll
        for (int n = 0; n < 8; n++) {
            const int c0 = n * 8 + tig * 2;
            const float mg0 = mng[c0], mg1 = mng[c0 + 1];
            float p00 = __expf(S[n][0] + btc[d0p[c0]] + mg0);
            float p01 = __expf(S[n][1] + btc[d0p[c0 + 1]] + mg1);
            float p10 = __expf(S[n][2] + btc[d1p[c0]] + mg0);
            float p11 = __expf(S[n][3] + btc[d1p[c0 + 1]] + mg1);
            __half2 h0 = __floats2half2_rn(p00, p01);
            __half2 h1 = __floats2half2_rn(p10, p11);
            // lsum must match what PV actually sums: use the half-rounded values
            float2 f0 = __half22float2(h0), f1 = __half22float2(h1);
            lsum0 += f0.x + f0.y;
            lsum1 += f1.x + f1.y;
            *(__half2*)(Psb + prow * 144 + c0 * 2) = h0;
            *(__half2*)(Psb + (prow + 8) * 144 + c0 * 2) = h1;
        }
        __syncwarp();
        if (kt < kt0 + 15) { stage_dm(kt + 1); CP_COMMIT(); }

        // ---- O += P @ V (4 k16 steps; p = d-pair tile of 16)
#pragma unroll
        for (int kk = 0; kk < 4; kk++) {
            uint32_t Pa[4];
            ldsm4(Pa, pbase + kk * 32);
            uint32_t Vf[4][4];
#pragma unroll
            for (int p = 0; p < 4; p++) ldsm4(Vf[p], vbase + p * 2304 + kk * 32);
#pragma unroll
            for (int p = 0; p < 4; p++) {
                mma16(O[2 * p], Pa, &Vf[p][0]);
                mma16(O[2 * p + 1], Pa, &Vf[p][2]);
            }
        }
    }

    // ---- epilogue: quad-reduce lsum, write UNNORMALIZED partials (R13 scheme)
    lsum0 += __shfl_xor_sync(0xffffffffu, lsum0, 1);
    lsum0 += __shfl_xor_sync(0xffffffffu, lsum0, 2);
    lsum1 += __shfl_xor_sync(0xffffffffu, lsum1, 1);
    lsum1 += __shfl_xor_sync(0xffffffffu, lsum1, 2);
    const size_t rbase = bh * 2048 + qt * 128 + w * 16;
    float* dst = g_part + (size_t)sp * 3145728 + rbase * 64;
#pragma unroll
    for (int n = 0; n < 8; n++) {
        const int c0 = n * 8 + tig * 2;
        *(float2*)&dst[gid * 64 + c0] = make_float2(O[n][0], O[n][1]);
        *(float2*)&dst[(gid + 8) * 64 + c0] = make_float2(O[n][2], O[n][3]);
    }
    if (tig == 0) {
        g_lsum[sp * 49152 + rbase + gid] = lsum0;
        g_lsum[sp * 49152 + rbase + gid + 8] = lsum1;
    }
}

// =============================================================================
// Kernel 2b: combine split-K partials -> g_ao (validated R13)
// =============================================================================
__global__ void combine_k() {
    const int i = (blockIdx.x * 256 + threadIdx.x) * 4;
    const int b = i / (2048 * 768);
    const int rem = i - b * 2048 * 768;
    const int n = rem / 768;
    const int c = rem - n * 768;
    const int h = c >> 6, hd = c & 63;
    const size_t row = ((size_t)(b * 12 + h)) * 2048 + n;
    const size_t p = row * 64 + hd;
    float4 o1 = *(const float4*)(g_part + p);
    float4 o2 = *(const float4*)(g_part + 3145728 + p);
    const float inv = 1.0f / (g_lsum[row] + g_lsum[49152 + row]);
    *(float4*)(g_ao + i) = make_float4(to_tf32((o1.x + o2.x) * inv),
                                       to_tf32((o1.y + o2.y) * inv),
                                       to_tf32((o1.z + o2.z) * inv),
                                       to_tf32((o1.w + o2.w) * inv));
}

// =============================================================================
extern "C" void kernel_launch(void* const* d_in, const int* in_sizes, int n_in,
                              void* d_out, int out_size) {
    const float* x         = (const float*)d_in[0];
    const int* dist        = (const int*)d_in[1];
    const unsigned int* mk = (const unsigned int*)d_in[2];
    const float* qkv_w     = (const float*)d_in[3];
    const float* qkv_b     = (const float*)d_in[4];
    const float* out_w     = (const float*)d_in[5];
    const float* out_b     = (const float*)d_in[6];
    const float* bt        = (const float*)d_in[7];
    float* out             = (float*)d_out;

    mask_prep<<<1, 256>>>(mk);
    dist_pack<<<4096, 256>>>(dist);
    round_all<<<5376, 256>>>(x, qkv_w, out_w);

    dim3 g1(18, 32);
    gemm_tc<<<g1, 256>>>(nullptr, nullptr, qkv_b, nullptr, 2304, 0);

    dim3 gt(32, 24);
    v_transpose<<<gt, 256>>>();

    cudaFuncSetAttribute(attn_mma, cudaFuncAttributeMaxDynamicSharedMemorySize, ATTN_SMEM);
    dim3 g2(16, 12, 4);
    attn_mma<<<g2, 256, ATTN_SMEM>>>(bt);

    combine_k<<<3072, 256>>>();

    dim3 g3(6, 32);
    gemm_tc<<<g3, 256>>>(nullptr, nullptr, out_b, out, 768, 1);
}

// round 15
// speedup vs baseline: 1.5459x; 1.1582x over previous
#include <cuda_runtime.h>
#include <cuda_fp16.h>
#include <cstdint>

// ---------------- scratch (allocation-free rule: __device__ globals) ----------
// g_q/g_k/g_v : half [B,H,N,64] (q pre-scaled 0.125)  g_vt : half [B,H,64,N]
// g_xh : half x [4096,768]   g_wt : half qkv_w^T [2304,768]   g_w2t : half out_w^T [768,768]
// g_aoh : half attention output [B*N,768]
__device__ __half g_q[2 * 12 * 2048 * 64];
__device__ __half g_k[2 * 12 * 2048 * 64];
__device__ __half g_v[2 * 12 * 2048 * 64];
__device__ __half g_vt[2 * 12 * 64 * 2048];
__device__ __half g_xh[2 * 2048 * 768];
__device__ __half g_wt[2304 * 768];
__device__ __half g_w2t[768 * 768];
__device__ __half g_aoh[2 * 2048 * 768];
__device__ float g_part[2 * 2 * 12 * 2048 * 64];    // [split][bh*2048+n][64]
__device__ float g_lsum[2 * 2 * 12 * 2048];         // [split][bh*2048+n]
__device__ float g_mneg[2 * 2048];                  // 0 or -1e30 per key
__device__ unsigned char g_dist8[2 * 2048 * 2048];  // clipped dist, 1 byte

// fp16 k16 mma (validated R14): same 11-bit mantissa as tf32, 2x rate, fp32 accum
__device__ __forceinline__ void mma16(float* c, const uint32_t* a, const uint32_t* b) {
    asm("mma.sync.aligned.m16n8k16.row.col.f32.f16.f16.f32 "
        "{%0,%1,%2,%3},{%4,%5,%6,%7},{%8,%9},{%0,%1,%2,%3};"
        : "+f"(c[0]), "+f"(c[1]), "+f"(c[2]), "+f"(c[3])
        : "r"(a[0]), "r"(a[1]), "r"(a[2]), "r"(a[3]), "r"(b[0]), "r"(b[1]));
}
__device__ __forceinline__ uint32_t smem_u32(const void* p) {
    uint32_t a;
    asm("{ .reg .u64 t; cvta.to.shared.u64 t, %1; cvt.u32.u64 %0, t; }" : "=r"(a) : "l"(p));
    return a;
}
__device__ __forceinline__ void ldsm4(uint32_t* r, uint32_t addr) {
    asm volatile("ldmatrix.sync.aligned.m8n8.x4.shared.b16 {%0,%1,%2,%3}, [%4];"
                 : "=r"(r[0]), "=r"(r[1]), "=r"(r[2]), "=r"(r[3]) : "r"(addr));
}
__device__ __forceinline__ void cpa16(uint32_t saddr, const void* g) {
    asm volatile("cp.async.cg.shared.global [%0], [%1], 16;" :: "r"(saddr), "l"(g));
}
#define CP_COMMIT() asm volatile("cp.async.commit_group;" ::: "memory")
#define CP_WAIT0()  asm volatile("cp.async.wait_group 0;" ::: "memory")

// =============================================================================
// Kernel 0a: mask dtype sniffer + conversion (validated R3)
// =============================================================================
__global__ void mask_prep(const unsigned int* __restrict__ mw) {
    const int tid = threadIdx.x;
    int ok_int = 1, ok_flt = 1;
    for (int i = tid; i < 1024; i += 256) {
        unsigned int v = mw[i];
        if (v != 0u && v != 1u) ok_int = 0;
        if (v != 0u && v != 0x3F800000u) ok_flt = 0;
    }
    ok_int = __syncthreads_and(ok_int);
    ok_flt = __syncthreads_and(ok_flt);
    if (ok_int) {
        const int* m = (const int*)mw;
        for (int i = tid; i < 4096; i += 256) g_mneg[i] = m[i] ? -1e30f : 0.0f;
    } else if (ok_flt) {
        const float* m = (const float*)mw;
        for (int i = tid; i < 4096; i += 256) g_mneg[i] = (m[i] != 0.0f) ? -1e30f : 0.0f;
    } else {
        const unsigned char* m = (const unsigned char*)mw;
        for (int i = tid; i < 4096; i += 256) g_mneg[i] = m[i] ? -1e30f : 0.0f;
    }
}

// =============================================================================
// Kernel 0b: pack dist int32 -> clipped uint8 (validated R6)
// =============================================================================
__global__ void dist_pack(const int* __restrict__ dist) {
    size_t i = ((size_t)blockIdx.x * 256 + threadIdx.x) * 8;
    int4 a = *(const int4*)(dist + i);
    int4 b = *(const int4*)(dist + i + 4);
    unsigned c0 = (unsigned)min(max(a.x, 0), 31) | ((unsigned)min(max(a.y, 0), 31) << 8) |
                  ((unsigned)min(max(a.z, 0), 31) << 16) | ((unsigned)min(max(a.w, 0), 31) << 24);
    unsigned c1 = (unsigned)min(max(b.x, 0), 31) | ((unsigned)min(max(b.y, 0), 31) << 8) |
                  ((unsigned)min(max(b.z, 0), 31) << 16) | ((unsigned)min(max(b.w, 0), 31) << 24);
    *(uint2*)(g_dist8 + i) = make_uint2(c0, c1);
}

// =============================================================================
// Kernel 0c (R15): x -> half
// =============================================================================
__global__ void conv_x(const float* __restrict__ x) {
    size_t i = ((size_t)blockIdx.x * 256 + threadIdx.x) * 8;
    float4 a = *(const float4*)(x + i);
    float4 b = *(const float4*)(x + i + 4);
    __half2* d = (__half2*)(g_xh + i);
    d[0] = __floats2half2_rn(a.x, a.y);
    d[1] = __floats2half2_rn(a.z, a.w);
    d[2] = __floats2half2_rn(b.x, b.y);
    d[3] = __floats2half2_rn(b.z, b.w);
}

// =============================================================================
// Kernel 0d (R15): W [768,N] float -> W^T [N,768] half (B tiles become [n][k]
// rows, loadable with the attention-validated plain-ldsm B-frag path).
// =============================================================================
__global__ void wtrans(const float* __restrict__ src, int N, int which) {
    __shared__ __half t[32][33];
    const int n0 = blockIdx.x * 32, k0 = blockIdx.y * 32;
    const int tx = threadIdx.x & 31, ty = threadIdx.x >> 5;
    for (int i = ty; i < 32; i += 8)
        t[i][tx] = __float2half(src[(size_t)(k0 + i) * N + n0 + tx]);
    __syncthreads();
    __half* dst = which ? g_w2t : g_wt;
    for (int i = ty; i < 32; i += 8)
        dst[(size_t)(n0 + i) * 768 + k0 + tx] = t[tx][i];
}

// =============================================================================
// Kernel 1 (R15): fp16 m16n8k16 GEMM for both projections.
// C[4096,N] = A[4096,768]h @ Wt[N,768]h^T + b ; 128x128 tile, BK=32.
// A [m][k] and B [n][k] both pitch-80B rows (20-word pitch: LDSM phases hit
// distinct bank groups {0,20,8,28,16,4,24,12}); cp.async double-buffered.
// mode 0: A=g_xh, Wt=g_wt, scatter half q/k/v (Q*0.125).
// mode 1: A=g_aoh, Wt=g_w2t, out float + bias.
// =============================================================================
__global__ __launch_bounds__(256) void gemm_fp16(const float* __restrict__ Bv,
                                                 float* __restrict__ outp,
                                                 int N, int mode) {
    const __half *A, *Wt;
    if (mode == 0) { A = g_xh; Wt = g_wt; }     // device-side symbols (R7 lesson)
    else           { A = g_aoh; Wt = g_w2t; }
    __shared__ __half As[2][128][40];           // 80B pitch
    __shared__ __half Bs[2][128][40];
    const int tid = threadIdx.x, w = tid >> 5, l = tid & 31;
    const int gid = l >> 2, tig = l & 3;
    const int wm = w >> 2, wn = w & 3;          // 2 x 4 warp grid, warp tile 64x32
    const int bM = blockIdx.y * 128, bN = blockIdx.x * 128;
    const uint32_t sb_a = smem_u32(&As[0][0][0]);
    const uint32_t sb_b = smem_u32(&Bs[0][0][0]);

    auto stage = [&](int k0, int buf) {
#pragma unroll
        for (int j = 0; j < 2; j++) {           // 128 rows x 64B each for A and B
            int c = tid + j * 256, r = c >> 2, o = (c & 3) * 16;
            cpa16(sb_a + buf * 10240 + r * 80 + o,
                  (const char*)(A + (size_t)(bM + r) * 768) + k0 * 2 + o);
            cpa16(sb_b + buf * 10240 + r * 80 + o,
                  (const char*)(Wt + (size_t)(bN + r) * 768) + k0 * 2 + o);
        }
    };

    float acc[4][4][4];
#pragma unroll
    for (int mi = 0; mi < 4; mi++)
#pragma unroll
        for (int ni = 0; ni < 4; ni++)
#pragma unroll
            for (int j = 0; j < 4; j++) acc[mi][ni][j] = 0.f;

    // LDSM lane maps (validated R14 attention: A-frag = P map, B-frag = K map)
    const uint32_t prowA = (l & 7) + ((l >> 3) & 1) * 8;
    const uint32_t pcolA = ((l >> 4) & 1) * 16;
    const uint32_t rowB = (l & 7) + ((l >> 4) & 1) * 8;
    const uint32_t colB = ((l >> 3) & 1) * 16;

    stage(0, 0);
    CP_COMMIT();

    for (int ks = 0; ks < 24; ks++) {
        CP_WAIT0();
        __syncthreads();  // tile ks visible; ks-1 drained
        if (ks < 23) { stage((ks + 1) * 32, (ks + 1) & 1); CP_COMMIT(); }
        const uint32_t abase = sb_a + (ks & 1) * 10240;
        const uint32_t bbase = sb_b + (ks & 1) * 10240;

#pragma unroll
        for (int kk = 0; kk < 2; kk++) {
            uint32_t Af[4][4], Bf[2][4];
#pragma unroll
            for (int mi = 0; mi < 4; mi++)
                ldsm4(Af[mi], abase + (wm * 64 + mi * 16 + prowA) * 80 + kk * 32 + pcolA);
#pragma unroll
            for (int bi = 0; bi < 2; bi++)
                ldsm4(Bf[bi], bbase + (wn * 32 + bi * 16 + rowB) * 80 + kk * 32 + colB);
#pragma unroll
            for (int mi = 0; mi < 4; mi++) {
                mma16(acc[mi][0], Af[mi], &Bf[0][0]);
                mma16(acc[mi][1], Af[mi], &Bf[0][2]);
                mma16(acc[mi][2], Af[mi], &Bf[1][0]);
                mma16(acc[mi][3], Af[mi], &Bf[1][2]);
            }
        }
    }

    // ---- epilogue (structure validated R8-R14)
#pragma unroll
    for (int ni = 0; ni < 4; ni++) {
        const int col0 = bN + wn * 32 + ni * 8 + tig * 2;
        const float b0 = Bv[col0], b1 = Bv[col0 + 1];
        if (mode == 0) {
            const int which = col0 / 768;
            const int rem = col0 % 768;
            const int hh = rem / 64, hd0 = rem % 64;
            __half* dst = (which == 0) ? g_q : (which == 1 ? g_k : g_v);
            const float qs = (which == 0) ? 0.125f : 1.0f;
#pragma unroll
            for (int mi = 0; mi < 4; mi++) {
                const int row = bM + wm * 64 + mi * 16 + gid;
                const int bidx = row >> 11, n = row & 2047;
                __half* p = dst + ((((size_t)bidx * 12 + hh) * 2048 + n) * 64 + hd0);
                *(__half2*)p =
                    __floats2half2_rn((acc[mi][ni][0] + b0) * qs, (acc[mi][ni][1] + b1) * qs);
                const int row2 = row + 8;
                const int bidx2 = row2 >> 11, n2 = row2 & 2047;
                __half* p2 = dst + ((((size_t)bidx2 * 12 + hh) * 2048 + n2) * 64 + hd0);
                *(__half2*)p2 =
                    __floats2half2_rn((acc[mi][ni][2] + b0) * qs, (acc[mi][ni][3] + b1) * qs);
            }
        } else {
#pragma unroll
            for (int mi = 0; mi < 4; mi++) {
                const int row = bM + wm * 64 + mi * 16 + gid;
                *(float2*)(outp + (size_t)row * 768 + col0) =
                    make_float2(acc[mi][ni][0] + b0, acc[mi][ni][1] + b1);
                *(float2*)(outp + (size_t)(row + 8) * 768 + col0) =
                    make_float2(acc[mi][ni][2] + b0, acc[mi][ni][3] + b1);
            }
        }
    }
}

// =============================================================================
// Kernel 1b: transpose V (half) -> g_vt [B,H,64,N] (validated R14)
// =============================================================================
__global__ __launch_bounds__(256) void v_transpose() {
    __shared__ __half smh[64 * 66];
    const int n0 = blockIdx.x * 64;
    const int bh = blockIdx.y;
    const __half2* s2 = (const __half2*)(g_v + ((size_t)bh * 2048 + n0) * 64);
    for (int v = threadIdx.x; v < 2048; v += 256) {
        int i = v >> 5, d2 = v & 31;
        __half2 h = s2[i * 32 + d2];
        smh[(2 * d2) * 66 + i] = __low2half(h);
        smh[(2 * d2 + 1) * 66 + i] = __high2half(h);
    }
    __syncthreads();
    __half2* d2p = (__half2*)(g_vt + (size_t)bh * 64 * 2048 + n0);
    for (int v = threadIdx.x; v < 2048; v += 256) {
        int d = v >> 5, j = v & 31;
        d2p[(size_t)d * 1024 + j] = __halves2half2(smh[d * 66 + 2 * j], smh[d * 66 + 2 * j + 1]);
    }
}

// =============================================================================
// Kernel 2: fp16 m16n8k16 flash attention, split-K (validated R14, unchanged)
// =============================================================================
static constexpr int VT_REL = 9216;
static constexpr int MNG_REL = 18432;
static constexpr int STG_SZ = 18688;
static constexpr int DS_OFF = 37376;
static constexpr int PS_OFF = 45568;
static constexpr int BT_OFF = 64000;
static constexpr int ATTN_SMEM = 64128;

__global__ __launch_bounds__(256, 2) void attn_mma(const float* __restrict__ bias_table) {
    extern __shared__ char smem[];
    const uint32_t sb = smem_u32(smem);
    unsigned char* Ds = (unsigned char*)(smem + DS_OFF);
    char* Psb = smem + PS_OFF;
    float* btc = (float*)(smem + BT_OFF);

    const int tid = threadIdx.x, w = tid >> 5, l = tid & 31;
    const int gid = l >> 2, tig = l & 3;
    const int qt = blockIdx.x, h = blockIdx.y;
    const int b = blockIdx.z >> 1, sp = blockIdx.z & 1;
    const int kt0 = sp * 16;
    const size_t bh = (size_t)b * 12 + h;

    const char* kgbase = (const char*)(g_k + bh * 2048 * 64);
    const char* vgbase = (const char*)(g_vt + bh * 64 * 2048);
    const unsigned char* dgbase = g_dist8 + (size_t)(b * 2048 + qt * 128) * 2048;

    auto stage_kv = [&](int kt, int buf) {
        const uint32_t base = sb + buf * STG_SZ;
#pragma unroll
        for (int j = 0; j < 2; j++) {
            int c = tid + j * 256, r = c >> 3, o = (c & 7) * 16;
            cpa16(base + r * 144 + o, kgbase + (size_t)(kt * 64 + r) * 128 + o);
        }
#pragma unroll
        for (int j = 0; j < 2; j++) {
            int c = tid + j * 256, r = c >> 3, o = (c & 7) * 16;
            cpa16(base + VT_REL + r * 144 + o, vgbase + (size_t)r * 4096 + kt * 128 + o);
        }
        if (tid < 16) cpa16(base + MNG_REL + tid * 16, g_mneg + b * 2048 + kt * 64 + tid * 4);
    };
    auto stage_dm = [&](int kt) {
#pragma unroll
        for (int j = 0; j < 2; j++) {
            int c = l + j * 32, r = w * 16 + (c >> 2), o = (c & 3) * 16;
            cpa16(sb + DS_OFF + r * 64 + o, dgbase + (size_t)r * 2048 + kt * 64 + o);
        }
    };

    uint32_t Qa[4][4];
    {
        const char* qb = (const char*)(g_q + (bh * 2048 + qt * 128 + w * 16) * 64);
#pragma unroll
        for (int s = 0; s < 4; s++) {
            const int o = s * 32 + tig * 4;
            Qa[s][0] = *(const uint32_t*)(qb + gid * 128 + o);
            Qa[s][1] = *(const uint32_t*)(qb + (gid + 8) * 128 + o);
            Qa[s][2] = *(const uint32_t*)(qb + gid * 128 + o + 16);
            Qa[s][3] = *(const uint32_t*)(qb + (gid + 8) * 128 + o + 16);
        }
    }
    if (tid < 32) btc[tid] = bias_table[tid * 12 + h];

    const uint32_t rowB = (l & 7) + ((l >> 4) & 1) * 8;
    const uint32_t colB = ((l >> 3) & 1) * 16;
    const uint32_t kvoff = rowB * 144 + colB;
    const uint32_t prowA = (l & 7) + ((l >> 3) & 1) * 8;
    const uint32_t pcolA = ((l >> 4) & 1) * 16;
    const uint32_t pbase = sb + PS_OFF + (w * 16 + prowA) * 144 + pcolA;

    float O[8][4];
#pragma unroll
    for (int n = 0; n < 8; n++)
#pragma unroll
        for (int j = 0; j < 4; j++) O[n][j] = 0.f;
    float lsum0 = 0.f, lsum1 = 0.f;

    stage_kv(kt0, 0);
    stage_dm(kt0);
    CP_COMMIT();

    for (int kt = kt0; kt < kt0 + 16; kt++) {
        CP_WAIT0();
        __syncthreads();
        if (kt < kt0 + 15) { stage_kv(kt + 1, (kt + 1) & 1); CP_COMMIT(); }

        const uint32_t stg = sb + (kt & 1) * STG_SZ;
        const uint32_t kbase = stg + kvoff;
        const uint32_t vbase = stg + VT_REL + kvoff;
        const float* mng = (const float*)(smem + (kt & 1) * STG_SZ + MNG_REL);

        float S[8][4];
#pragma unroll
        for (int n = 0; n < 8; n++)
#pragma unroll
            for (int j = 0; j < 4; j++) S[n][j] = 0.f;
#pragma unroll
        for (int s = 0; s < 4; s++) {
            uint32_t Bf[4][4];
#pragma unroll
            for (int p = 0; p < 4; p++) ldsm4(Bf[p], kbase + p * 2304 + s * 32);
#pragma unroll
            for (int p = 0; p < 4; p++) {
                mma16(S[2 * p], Qa[s], &Bf[p][0]);
                mma16(S[2 * p + 1], Qa[s], &Bf[p][2]);
            }
        }

        const unsigned char* d0p = Ds + (w * 16 + gid) * 64;
        const unsigned char* d1p = Ds + (w * 16 + gid + 8) * 64;
        const int prow = w * 16 + gid;
#pragma unroll
        for (int n = 0; n < 8; n++) {
            const int c0 = n * 8 + tig * 2;
            const float mg0 = mng[c0], mg1 = mng[c0 + 1];
            float p00 = __expf(S[n][0] + btc[d0p[c0]] + mg0);
            float p01 = __expf(S[n][1] + btc[d0p[c0 + 1]] + mg1);
            float p10 = __expf(S[n][2] + btc[d1p[c0]] + mg0);
            float p11 = __expf(S[n][3] + btc[d1p[c0 + 1]] + mg1);
            __half2 h0 = __floats2half2_rn(p00, p01);
            __half2 h1 = __floats2half2_rn(p10, p11);
            float2 f0 = __half22float2(h0), f1 = __half22float2(h1);
            lsum0 += f0.x + f0.y;
            lsum1 += f1.x + f1.y;
            *(__half2*)(Psb + prow * 144 + c0 * 2) = h0;
            *(__half2*)(Psb + (prow + 8) * 144 + c0 * 2) = h1;
        }
        __syncwarp();
        if (kt < kt0 + 15) { stage_dm(kt + 1); CP_COMMIT(); }

#pragma unroll
        for (int kk = 0; kk < 4; kk++) {
            uint32_t Pa[4];
            ldsm4(Pa, pbase + kk * 32);
            uint32_t Vf[4][4];
#pragma unroll
            for (int p = 0; p < 4; p++) ldsm4(Vf[p], vbase + p * 2304 + kk * 32);
#pragma unroll
            for (int p = 0; p < 4; p++) {
                mma16(O[2 * p], Pa, &Vf[p][0]);
                mma16(O[2 * p + 1], Pa, &Vf[p][2]);
            }
        }
    }

    lsum0 += __shfl_xor_sync(0xffffffffu, lsum0, 1);
    lsum0 += __shfl_xor_sync(0xffffffffu, lsum0, 2);
    lsum1 += __shfl_xor_sync(0xffffffffu, lsum1, 1);
    lsum1 += __shfl_xor_sync(0xffffffffu, lsum1, 2);
    const size_t rbase = bh * 2048 + qt * 128 + w * 16;
    float* dst = g_part + (size_t)sp * 3145728 + rbase * 64;
#pragma unroll
    for (int n = 0; n < 8; n++) {
        const int c0 = n * 8 + tig * 2;
        *(float2*)&dst[gid * 64 + c0] = make_float2(O[n][0], O[n][1]);
        *(float2*)&dst[(gid + 8) * 64 + c0] = make_float2(O[n][2], O[n][3]);
    }
    if (tig == 0) {
        g_lsum[sp * 49152 + rbase + gid] = lsum0;
        g_lsum[sp * 49152 + rbase + gid + 8] = lsum1;
    }
}

// =============================================================================
// Kernel 2b: combine split-K partials -> HALF g_aoh (proj GEMM A input)
// =============================================================================
__global__ void combine_k() {
    const int i = (blockIdx.x * 256 + threadIdx.x) * 4;
    const int b = i / (2048 * 768);
    const int rem = i - b * 2048 * 768;
    const int n = rem / 768;
    const int c = rem - n * 768;
    const int h = c >> 6, hd = c & 63;
    const size_t row = ((size_t)(b * 12 + h)) * 2048 + n;
    const size_t p = row * 64 + hd;
    float4 o1 = *(const float4*)(g_part + p);
    float4 o2 = *(const float4*)(g_part + 3145728 + p);
    const float inv = 1.0f / (g_lsum[row] + g_lsum[49152 + row]);
    __half2* d = (__half2*)(g_aoh + i);
    d[0] = __floats2half2_rn((o1.x + o2.x) * inv, (o1.y + o2.y) * inv);
    d[1] = __floats2half2_rn((o1.z + o2.z) * inv, (o1.w + o2.w) * inv);
}

// =============================================================================
extern "C" void kernel_launch(void* const* d_in, const int* in_sizes, int n_in,
                              void* d_out, int out_size) {
    const float* x         = (const float*)d_in[0];
    const int* dist        = (const int*)d_in[1];
    const unsigned int* mk = (const unsigned int*)d_in[2];
    const float* qkv_w     = (const float*)d_in[3];
    const float* qkv_b     = (const float*)d_in[4];
    const float* out_w     = (const float*)d_in[5];
    const float* out_b     = (const float*)d_in[6];
    const float* bt        = (const float*)d_in[7];
    float* out             = (float*)d_out;

    mask_prep<<<1, 256>>>(mk);
    dist_pack<<<4096, 256>>>(dist);
    conv_x<<<1536, 256>>>(x);
    wtrans<<<dim3(72, 24), 256>>>(qkv_w, 2304, 0);
    wtrans<<<dim3(24, 24), 256>>>(out_w, 768, 1);

    dim3 g1(18, 32);
    gemm_fp16<<<g1, 256>>>(qkv_b, nullptr, 2304, 0);

    dim3 gt(32, 24);
    v_transpose<<<gt, 256>>>();

    cudaFuncSetAttribute(attn_mma, cudaFuncAttributeMaxDynamicSharedMemorySize, ATTN_SMEM);
    dim3 g2(16, 12, 4);
    attn_mma<<<g2, 256, ATTN_SMEM>>>(bt);

    combine_k<<<3072, 256>>>();

    dim3 g3(6, 32);
    gemm_fp16<<<g3, 256>>>(out_b, out, 768, 1);
}

// round 16
// speedup vs baseline: 1.7267x; 1.1169x over previous
#include <cuda_runtime.h>
#include <cuda_fp16.h>
#include <cstdint>

// ---------------- scratch (allocation-free rule: __device__ globals) ----------
__device__ __half g_q[2 * 12 * 2048 * 64];
__device__ __half g_k[2 * 12 * 2048 * 64];
__device__ __half g_v[2 * 12 * 2048 * 64];
__device__ __half g_vt[2 * 12 * 64 * 2048];
__device__ __half g_xh[2 * 2048 * 768];
__device__ __half g_wt[2304 * 768];
__device__ __half g_w2t[768 * 768];
__device__ __half g_aoh[2 * 2048 * 768];
__device__ float g_part[2 * 2 * 12 * 2048 * 64];    // [split][bh*2048+n][64]
__device__ float g_lsum[2 * 2 * 12 * 2048];         // [split][bh*2048+n]
__device__ float g_mneg[2 * 2048];                  // 0 or -1e30 per key
__device__ unsigned char g_dist8[2 * 2048 * 2048];  // clipped dist, 1 byte

// fp16 k16 mma (validated R14/R15): tf32 mantissa, 2x rate, fp32 accum
__device__ __forceinline__ void mma16(float* c, const uint32_t* a, const uint32_t* b) {
    asm("mma.sync.aligned.m16n8k16.row.col.f32.f16.f16.f32 "
        "{%0,%1,%2,%3},{%4,%5,%6,%7},{%8,%9},{%0,%1,%2,%3};"
        : "+f"(c[0]), "+f"(c[1]), "+f"(c[2]), "+f"(c[3])
        : "r"(a[0]), "r"(a[1]), "r"(a[2]), "r"(a[3]), "r"(b[0]), "r"(b[1]));
}
__device__ __forceinline__ uint32_t smem_u32(const void* p) {
    uint32_t a;
    asm("{ .reg .u64 t; cvta.to.shared.u64 t, %1; cvt.u32.u64 %0, t; }" : "=r"(a) : "l"(p));
    return a;
}
__device__ __forceinline__ void ldsm4(uint32_t* r, uint32_t addr) {
    asm volatile("ldmatrix.sync.aligned.m8n8.x4.shared.b16 {%0,%1,%2,%3}, [%4];"
                 : "=r"(r[0]), "=r"(r[1]), "=r"(r[2]), "=r"(r[3]) : "r"(addr));
}
__device__ __forceinline__ void cpa16(uint32_t saddr, const void* g) {
    asm volatile("cp.async.cg.shared.global [%0], [%1], 16;" :: "r"(saddr), "l"(g));
}
#define CP_COMMIT() asm volatile("cp.async.commit_group;" ::: "memory")
#define CP_WAIT0()  asm volatile("cp.async.wait_group 0;" ::: "memory")
#define CP_WAIT1()  asm volatile("cp.async.wait_group 1;" ::: "memory")

// =============================================================================
// Kernel 0 (R16): ALL prep fused into one launch, block-range dispatch.
//  [0,4096)      dist_pack  (validated R6)
//  [4096,5632)   conv_x     (validated R15)
//  [5632,7360)   wtrans qkv_w (72 x 24 tiles)   (validated R15)
//  [7360,7936)   wtrans out_w (24 x 24 tiles)
//  7936          mask_prep  (validated R3)
// =============================================================================
__global__ void prep_all(const int* __restrict__ dist,
                         const float* __restrict__ x,
                         const float* __restrict__ w1,
                         const float* __restrict__ w2,
                         const unsigned int* __restrict__ mw) {
    __shared__ __half t[32][33];
    const int bid = blockIdx.x;
    const int tid = threadIdx.x;

    if (bid < 4096) {  // ---- dist_pack
        size_t i = ((size_t)bid * 256 + tid) * 8;
        int4 a = *(const int4*)(dist + i);
        int4 b = *(const int4*)(dist + i + 4);
        unsigned c0 = (unsigned)min(max(a.x, 0), 31) | ((unsigned)min(max(a.y, 0), 31) << 8) |
                      ((unsigned)min(max(a.z, 0), 31) << 16) | ((unsigned)min(max(a.w, 0), 31) << 24);
        unsigned c1 = (unsigned)min(max(b.x, 0), 31) | ((unsigned)min(max(b.y, 0), 31) << 8) |
                      ((unsigned)min(max(b.z, 0), 31) << 16) | ((unsigned)min(max(b.w, 0), 31) << 24);
        *(uint2*)(g_dist8 + i) = make_uint2(c0, c1);
    } else if (bid < 5632) {  // ---- conv_x
        size_t i = ((size_t)(bid - 4096) * 256 + tid) * 8;
        float4 a = *(const float4*)(x + i);
        float4 b = *(const float4*)(x + i + 4);
        __half2* d = (__half2*)(g_xh + i);
        d[0] = __floats2half2_rn(a.x, a.y);
        d[1] = __floats2half2_rn(a.z, a.w);
        d[2] = __floats2half2_rn(b.x, b.y);
        d[3] = __floats2half2_rn(b.z, b.w);
    } else if (bid < 7936) {  // ---- wtrans (both weights)
        const int idx = bid - 5632;
        const float* src;
        __half* dst;
        int N, n0, k0;
        if (idx < 1728) { src = w1; dst = g_wt;  N = 2304; n0 = (idx % 72) * 32; k0 = (idx / 72) * 32; }
        else            { src = w2; dst = g_w2t; N = 768;  n0 = ((idx - 1728) % 24) * 32; k0 = ((idx - 1728) / 24) * 32; }
        const int tx = tid & 31, ty = tid >> 5;
        for (int i = ty; i < 32; i += 8)
            t[i][tx] = __float2half(src[(size_t)(k0 + i) * N + n0 + tx]);
        __syncthreads();
        for (int i = ty; i < 32; i += 8)
            dst[(size_t)(n0 + i) * 768 + k0 + tx] = t[tx][i];
    } else {  // ---- mask_prep (1 block)
        int ok_int = 1, ok_flt = 1;
        for (int i = tid; i < 1024; i += 256) {
            unsigned int v = mw[i];
            if (v != 0u && v != 1u) ok_int = 0;
            if (v != 0u && v != 0x3F800000u) ok_flt = 0;
        }
        ok_int = __syncthreads_and(ok_int);
        ok_flt = __syncthreads_and(ok_flt);
        if (ok_int) {
            const int* m = (const int*)mw;
            for (int i = tid; i < 4096; i += 256) g_mneg[i] = m[i] ? -1e30f : 0.0f;
        } else if (ok_flt) {
            const float* m = (const float*)mw;
            for (int i = tid; i < 4096; i += 256) g_mneg[i] = (m[i] != 0.0f) ? -1e30f : 0.0f;
        } else {
            const unsigned char* m = (const unsigned char*)mw;
            for (int i = tid; i < 4096; i += 256) g_mneg[i] = m[i] ? -1e30f : 0.0f;
        }
    }
}

// =============================================================================
// Kernel 1 (R16): fp16 GEMM, TRIPLE-buffered cp.async (depth-2 prefetch).
// Each tile now has ~2 k-steps of compute to land -> L2 latency hidden.
// Dynamic smem: A 3x10240 B + B 3x10240 B = 61440 B (static 48KB limit).
// =============================================================================
static constexpr int GEMM_SMEM = 61440;

__global__ __launch_bounds__(256) void gemm_fp16(const float* __restrict__ Bv,
                                                 float* __restrict__ outp,
                                                 int N, int mode) {
    const __half *A, *Wt;
    if (mode == 0) { A = g_xh; Wt = g_wt; }     // device-side symbols (R7 lesson)
    else           { A = g_aoh; Wt = g_w2t; }
    extern __shared__ char smem[];
    const int tid = threadIdx.x, w = tid >> 5, l = tid & 31;
    const int gid = l >> 2, tig = l & 3;
    const int wm = w >> 2, wn = w & 3;          // 2 x 4 warp grid, warp tile 64x32
    const int bM = blockIdx.y * 128, bN = blockIdx.x * 128;
    const uint32_t sb_a = smem_u32(smem);
    const uint32_t sb_b = sb_a + 30720;

    auto stage = [&](int k0, int buf) {
#pragma unroll
        for (int j = 0; j < 2; j++) {           // 128 rows x 64B each for A and B
            int c = tid + j * 256, r = c >> 2, o = (c & 3) * 16;
            cpa16(sb_a + buf * 10240 + r * 80 + o,
                  (const char*)(A + (size_t)(bM + r) * 768) + k0 * 2 + o);
            cpa16(sb_b + buf * 10240 + r * 80 + o,
                  (const char*)(Wt + (size_t)(bN + r) * 768) + k0 * 2 + o);
        }
    };

    float acc[4][4][4];
#pragma unroll
    for (int mi = 0; mi < 4; mi++)
#pragma unroll
        for (int ni = 0; ni < 4; ni++)
#pragma unroll
            for (int j = 0; j < 4; j++) acc[mi][ni][j] = 0.f;

    // LDSM lane maps (validated R14/R15)
    const uint32_t prowA = (l & 7) + ((l >> 3) & 1) * 8;
    const uint32_t pcolA = ((l >> 4) & 1) * 16;
    const uint32_t rowB = (l & 7) + ((l >> 4) & 1) * 8;
    const uint32_t colB = ((l >> 3) & 1) * 16;

    stage(0, 0);
    CP_COMMIT();
    stage(32, 1);
    CP_COMMIT();

    for (int ks = 0; ks < 24; ks++) {
        // pending = {tile ks, tile ks+1}; wait1 retires tile ks (wait0 at tail)
        if (ks < 23) CP_WAIT1(); else CP_WAIT0();
        __syncthreads();  // tile ks visible everywhere; buf (ks+2)%3 drained (used at ks-1)
        if (ks < 22) { stage((ks + 2) * 32, (ks + 2) % 3); CP_COMMIT(); }
        const int buf = ks % 3;
        const uint32_t abase = sb_a + buf * 10240;
        const uint32_t bbase = sb_b + buf * 10240;

#pragma unroll
        for (int kk = 0; kk < 2; kk++) {
            uint32_t Af[4][4], Bf[2][4];
#pragma unroll
            for (int mi = 0; mi < 4; mi++)
                ldsm4(Af[mi], abase + (wm * 64 + mi * 16 + prowA) * 80 + kk * 32 + pcolA);
#pragma unroll
            for (int bi = 0; bi < 2; bi++)
                ldsm4(Bf[bi], bbase + (wn * 32 + bi * 16 + rowB) * 80 + kk * 32 + colB);
#pragma unroll
            for (int mi = 0; mi < 4; mi++) {
                mma16(acc[mi][0], Af[mi], &Bf[0][0]);
                mma16(acc[mi][1], Af[mi], &Bf[0][2]);
                mma16(acc[mi][2], Af[mi], &Bf[1][0]);
                mma16(acc[mi][3], Af[mi], &Bf[1][2]);
            }
        }
    }

    // ---- epilogue (validated R8-R15)
#pragma unroll
    for (int ni = 0; ni < 4; ni++) {
        const int col0 = bN + wn * 32 + ni * 8 + tig * 2;
        const float b0 = Bv[col0], b1 = Bv[col0 + 1];
        if (mode == 0) {
            const int which = col0 / 768;
            const int rem = col0 % 768;
            const int hh = rem / 64, hd0 = rem % 64;
            __half* dst = (which == 0) ? g_q : (which == 1 ? g_k : g_v);
            const float qs = (which == 0) ? 0.125f : 1.0f;
#pragma unroll
            for (int mi = 0; mi < 4; mi++) {
                const int row = bM + wm * 64 + mi * 16 + gid;
                const int bidx = row >> 11, n = row & 2047;
                __half* p = dst + ((((size_t)bidx * 12 + hh) * 2048 + n) * 64 + hd0);
                *(__half2*)p =
                    __floats2half2_rn((acc[mi][ni][0] + b0) * qs, (acc[mi][ni][1] + b1) * qs);
                const int row2 = row + 8;
                const int bidx2 = row2 >> 11, n2 = row2 & 2047;
                __half* p2 = dst + ((((size_t)bidx2 * 12 + hh) * 2048 + n2) * 64 + hd0);
                *(__half2*)p2 =
                    __floats2half2_rn((acc[mi][ni][2] + b0) * qs, (acc[mi][ni][3] + b1) * qs);
            }
        } else {
#pragma unroll
            for (int mi = 0; mi < 4; mi++) {
                const int row = bM + wm * 64 + mi * 16 + gid;
                *(float2*)(outp + (size_t)row * 768 + col0) =
                    make_float2(acc[mi][ni][0] + b0, acc[mi][ni][1] + b1);
                *(float2*)(outp + (size_t)(row + 8) * 768 + col0) =
                    make_float2(acc[mi][ni][2] + b0, acc[mi][ni][3] + b1);
            }
        }
    }
}

// =============================================================================
// Kernel 1b: transpose V (half) -> g_vt [B,H,64,N] (validated R14)
// =============================================================================
__global__ __launch_bounds__(256) void v_transpose() {
    __shared__ __half smh[64 * 66];
    const int n0 = blockIdx.x * 64;
    const int bh = blockIdx.y;
    const __half2* s2 = (const __half2*)(g_v + ((size_t)bh * 2048 + n0) * 64);
    for (int v = threadIdx.x; v < 2048; v += 256) {
        int i = v >> 5, d2 = v & 31;
        __half2 h = s2[i * 32 + d2];
        smh[(2 * d2) * 66 + i] = __low2half(h);
        smh[(2 * d2 + 1) * 66 + i] = __high2half(h);
    }
    __syncthreads();
    __half2* d2p = (__half2*)(g_vt + (size_t)bh * 64 * 2048 + n0);
    for (int v = threadIdx.x; v < 2048; v += 256) {
        int d = v >> 5, j = v & 31;
        d2p[(size_t)d * 1024 + j] = __halves2half2(smh[d * 66 + 2 * j], smh[d * 66 + 2 * j + 1]);
    }
}

// =============================================================================
// Kernel 2: fp16 m16n8k16 flash attention, split-K (validated R14/R15, unchanged)
// =============================================================================
static constexpr int VT_REL = 9216;
static constexpr int MNG_REL = 18432;
static constexpr int STG_SZ = 18688;
static constexpr int DS_OFF = 37376;
static constexpr int PS_OFF = 45568;
static constexpr int BT_OFF = 64000;
static constexpr int ATTN_SMEM = 64128;

__global__ __launch_bounds__(256, 2) void attn_mma(const float* __restrict__ bias_table) {
    extern __shared__ char smem[];
    const uint32_t sb = smem_u32(smem);
    unsigned char* Ds = (unsigned char*)(smem + DS_OFF);
    char* Psb = smem + PS_OFF;
    float* btc = (float*)(smem + BT_OFF);

    const int tid = threadIdx.x, w = tid >> 5, l = tid & 31;
    const int gid = l >> 2, tig = l & 3;
    const int qt = blockIdx.x, h = blockIdx.y;
    const int b = blockIdx.z >> 1, sp = blockIdx.z & 1;
    const int kt0 = sp * 16;
    const size_t bh = (size_t)b * 12 + h;

    const char* kgbase = (const char*)(g_k + bh * 2048 * 64);
    const char* vgbase = (const char*)(g_vt + bh * 64 * 2048);
    const unsigned char* dgbase = g_dist8 + (size_t)(b * 2048 + qt * 128) * 2048;

    auto stage_kv = [&](int kt, int buf) {
        const uint32_t base = sb + buf * STG_SZ;
#pragma unroll
        for (int j = 0; j < 2; j++) {
            int c = tid + j * 256, r = c >> 3, o = (c & 7) * 16;
            cpa16(base + r * 144 + o, kgbase + (size_t)(kt * 64 + r) * 128 + o);
        }
#pragma unroll
        for (int j = 0; j < 2; j++) {
            int c = tid + j * 256, r = c >> 3, o = (c & 7) * 16;
            cpa16(base + VT_REL + r * 144 + o, vgbase + (size_t)r * 4096 + kt * 128 + o);
        }
        if (tid < 16) cpa16(base + MNG_REL + tid * 16, g_mneg + b * 2048 + kt * 64 + tid * 4);
    };
    auto stage_dm = [&](int kt) {
#pragma unroll
        for (int j = 0; j < 2; j++) {
            int c = l + j * 32, r = w * 16 + (c >> 2), o = (c & 3) * 16;
            cpa16(sb + DS_OFF + r * 64 + o, dgbase + (size_t)r * 2048 + kt * 64 + o);
        }
    };

    uint32_t Qa[4][4];
    {
        const char* qb = (const char*)(g_q + (bh * 2048 + qt * 128 + w * 16) * 64);
#pragma unroll
        for (int s = 0; s < 4; s++) {
            const int o = s * 32 + tig * 4;
            Qa[s][0] = *(const uint32_t*)(qb + gid * 128 + o);
            Qa[s][1] = *(const uint32_t*)(qb + (gid + 8) * 128 + o);
            Qa[s][2] = *(const uint32_t*)(qb + gid * 128 + o + 16);
            Qa[s][3] = *(const uint32_t*)(qb + (gid + 8) * 128 + o + 16);
        }
    }
    if (tid < 32) btc[tid] = bias_table[tid * 12 + h];

    const uint32_t rowB = (l & 7) + ((l >> 4) & 1) * 8;
    const uint32_t colB = ((l >> 3) & 1) * 16;
    const uint32_t kvoff = rowB * 144 + colB;
    const uint32_t prowA = (l & 7) + ((l >> 3) & 1) * 8;
    const uint32_t pcolA = ((l >> 4) & 1) * 16;
    const uint32_t pbase = sb + PS_OFF + (w * 16 + prowA) * 144 + pcolA;

    float O[8][4];
#pragma unroll
    for (int n = 0; n < 8; n++)
#pragma unroll
        for (int j = 0; j < 4; j++) O[n][j] = 0.f;
    float lsum0 = 0.f, lsum1 = 0.f;

    stage_kv(kt0, 0);
    stage_dm(kt0);
    CP_COMMIT();

    for (int kt = kt0; kt < kt0 + 16; kt++) {
        CP_WAIT0();
        __syncthreads();
        if (kt < kt0 + 15) { stage_kv(kt + 1, (kt + 1) & 1); CP_COMMIT(); }

        const uint32_t stg = sb + (kt & 1) * STG_SZ;
        const uint32_t kbase = stg + kvoff;
        const uint32_t vbase = stg + VT_REL + kvoff;
        const float* mng = (const float*)(smem + (kt & 1) * STG_SZ + MNG_REL);

        float S[8][4];
#pragma unroll
        for (int n = 0; n < 8; n++)
#pragma unroll
            for (int j = 0; j < 4; j++) S[n][j] = 0.f;
#pragma unroll
        for (int s = 0; s < 4; s++) {
            uint32_t Bf[4][4];
#pragma unroll
            for (int p = 0; p < 4; p++) ldsm4(Bf[p], kbase + p * 2304 + s * 32);
#pragma unroll
            for (int p = 0; p < 4; p++) {
                mma16(S[2 * p], Qa[s], &Bf[p][0]);
                mma16(S[2 * p + 1], Qa[s], &Bf[p][2]);
            }
        }

        const unsigned char* d0p = Ds + (w * 16 + gid) * 64;
        const unsigned char* d1p = Ds + (w * 16 + gid + 8) * 64;
        const int prow = w * 16 + gid;
#pragma unroll
        for (int n = 0; n < 8; n++) {
            const int c0 = n * 8 + tig * 2;
            const float mg0 = mng[c0], mg1 = mng[c0 + 1];
            float p00 = __expf(S[n][0] + btc[d0p[c0]] + mg0);
            float p01 = __expf(S[n][1] + btc[d0p[c0 + 1]] + mg1);
            float p10 = __expf(S[n][2] + btc[d1p[c0]] + mg0);
            float p11 = __expf(S[n][3] + btc[d1p[c0 + 1]] + mg1);
            __half2 h0 = __floats2half2_rn(p00, p01);
            __half2 h1 = __floats2half2_rn(p10, p11);
            float2 f0 = __half22float2(h0), f1 = __half22float2(h1);
            lsum0 += f0.x + f0.y;
            lsum1 += f1.x + f1.y;
            *(__half2*)(Psb + prow * 144 + c0 * 2) = h0;
            *(__half2*)(Psb + (prow + 8) * 144 + c0 * 2) = h1;
        }
        __syncwarp();
        if (kt < kt0 + 15) { stage_dm(kt + 1); CP_COMMIT(); }

#pragma unroll
        for (int kk = 0; kk < 4; kk++) {
            uint32_t Pa[4];
            ldsm4(Pa, pbase + kk * 32);
            uint32_t Vf[4][4];
#pragma unroll
            for (int p = 0; p < 4; p++) ldsm4(Vf[p], vbase + p * 2304 + kk * 32);
#pragma unroll
            for (int p = 0; p < 4; p++) {
                mma16(O[2 * p], Pa, &Vf[p][0]);
                mma16(O[2 * p + 1], Pa, &Vf[p][2]);
            }
        }
    }

    lsum0 += __shfl_xor_sync(0xffffffffu, lsum0, 1);
    lsum0 += __shfl_xor_sync(0xffffffffu, lsum0, 2);
    lsum1 += __shfl_xor_sync(0xffffffffu, lsum1, 1);
    lsum1 += __shfl_xor_sync(0xffffffffu, lsum1, 2);
    const size_t rbase = bh * 2048 + qt * 128 + w * 16;
    float* dst = g_part + (size_t)sp * 3145728 + rbase * 64;
#pragma unroll
    for (int n = 0; n < 8; n++) {
        const int c0 = n * 8 + tig * 2;
        *(float2*)&dst[gid * 64 + c0] = make_float2(O[n][0], O[n][1]);
        *(float2*)&dst[(gid + 8) * 64 + c0] = make_float2(O[n][2], O[n][3]);
    }
    if (tig == 0) {
        g_lsum[sp * 49152 + rbase + gid] = lsum0;
        g_lsum[sp * 49152 + rbase + gid + 8] = lsum1;
    }
}

// =============================================================================
// Kernel 2b: combine split-K partials -> HALF g_aoh (validated R15)
// =============================================================================
__global__ void combine_k() {
    const int i = (blockIdx.x * 256 + threadIdx.x) * 4;
    const int b = i / (2048 * 768);
    const int rem = i - b * 2048 * 768;
    const int n = rem / 768;
    const int c = rem - n * 768;
    const int h = c >> 6, hd = c & 63;
    const size_t row = ((size_t)(b * 12 + h)) * 2048 + n;
    const size_t p = row * 64 + hd;
    float4 o1 = *(const float4*)(g_part + p);
    float4 o2 = *(const float4*)(g_part + 3145728 + p);
    const float inv = 1.0f / (g_lsum[row] + g_lsum[49152 + row]);
    __half2* d = (__half2*)(g_aoh + i);
    d[0] = __floats2half2_rn((o1.x + o2.x) * inv, (o1.y + o2.y) * inv);
    d[1] = __floats2half2_rn((o1.z + o2.z) * inv, (o1.w + o2.w) * inv);
}

// =============================================================================
extern "C" void kernel_launch(void* const* d_in, const int* in_sizes, int n_in,
                              void* d_out, int out_size) {
    const float* x         = (const float*)d_in[0];
    const int* dist        = (const int*)d_in[1];
    const unsigned int* mk = (const unsigned int*)d_in[2];
    const float* qkv_w     = (const float*)d_in[3];
    const float* qkv_b     = (const float*)d_in[4];
    const float* out_w     = (const float*)d_in[5];
    const float* out_b     = (const float*)d_in[6];
    const float* bt        = (const float*)d_in[7];
    float* out             = (float*)d_out;

    prep_all<<<7937, 256>>>(dist, x, qkv_w, out_w, mk);

    cudaFuncSetAttribute(gemm_fp16, cudaFuncAttributeMaxDynamicSharedMemorySize, GEMM_SMEM);
    dim3 g1(18, 32);
    gemm_fp16<<<g1, 256, GEMM_SMEM>>>(qkv_b, nullptr, 2304, 0);

    dim3 gt(32, 24);
    v_transpose<<<gt, 256>>>();

    cudaFuncSetAttribute(attn_mma, cudaFuncAttributeMaxDynamicSharedMemorySize, ATTN_SMEM);
    dim3 g2(16, 12, 4);
    attn_mma<<<g2, 256, ATTN_SMEM>>>(bt);

    combine_k<<<3072, 256>>>();

    dim3 g3(6, 32);
    gemm_fp16<<<g3, 256, GEMM_SMEM>>>(out_b, out, 768, 1);
}

// round 17
// speedup vs baseline: 1.7725x; 1.0265x over previous
#include <cuda_runtime.h>
#include <cuda_fp16.h>
#include <cstdint>

// ---------------- scratch (allocation-free rule: __device__ globals) ----------
__device__ __half g_q[2 * 12 * 2048 * 64];
__device__ __half g_k[2 * 12 * 2048 * 64];
__device__ __half g_v[2 * 12 * 2048 * 64];
__device__ __half g_vt[2 * 12 * 64 * 2048];
__device__ __half g_xh[2 * 2048 * 768];
__device__ __half g_wt[2304 * 768];
__device__ __half g_w2t[768 * 768];
__device__ __half g_aoh[2 * 2048 * 768];
__device__ float g_part[2 * 2 * 12 * 2048 * 64];    // [split][bh*2048+n][64]
__device__ float g_lsum[2 * 2 * 12 * 2048];         // [split][bh*2048+n]
__device__ float g_mneg[2 * 2048];                  // 0 or -1e30 per key
__device__ unsigned char g_dist8[2 * 2048 * 2048];  // clipped dist, 1 byte

// fp16 k16 mma (validated R14/R15): tf32 mantissa, 2x rate, fp32 accum
__device__ __forceinline__ void mma16(float* c, const uint32_t* a, const uint32_t* b) {
    asm("mma.sync.aligned.m16n8k16.row.col.f32.f16.f16.f32 "
        "{%0,%1,%2,%3},{%4,%5,%6,%7},{%8,%9},{%0,%1,%2,%3};"
        : "+f"(c[0]), "+f"(c[1]), "+f"(c[2]), "+f"(c[3])
        : "r"(a[0]), "r"(a[1]), "r"(a[2]), "r"(a[3]), "r"(b[0]), "r"(b[1]));
}
__device__ __forceinline__ uint32_t smem_u32(const void* p) {
    uint32_t a;
    asm("{ .reg .u64 t; cvta.to.shared.u64 t, %1; cvt.u32.u64 %0, t; }" : "=r"(a) : "l"(p));
    return a;
}
__device__ __forceinline__ void ldsm4(uint32_t* r, uint32_t addr) {
    asm volatile("ldmatrix.sync.aligned.m8n8.x4.shared.b16 {%0,%1,%2,%3}, [%4];"
                 : "=r"(r[0]), "=r"(r[1]), "=r"(r[2]), "=r"(r[3]) : "r"(addr));
}
__device__ __forceinline__ void cpa16(uint32_t saddr, const void* g) {
    asm volatile("cp.async.cg.shared.global [%0], [%1], 16;" :: "r"(saddr), "l"(g));
}
#define CP_COMMIT() asm volatile("cp.async.commit_group;" ::: "memory")
#define CP_WAIT0()  asm volatile("cp.async.wait_group 0;" ::: "memory")
#define CP_WAIT1()  asm volatile("cp.async.wait_group 1;" ::: "memory")

// =============================================================================
// Kernel 0: ALL prep fused (validated R16)
// =============================================================================
__global__ void prep_all(const int* __restrict__ dist,
                         const float* __restrict__ x,
                         const float* __restrict__ w1,
                         const float* __restrict__ w2,
                         const unsigned int* __restrict__ mw) {
    __shared__ __half t[32][33];
    const int bid = blockIdx.x;
    const int tid = threadIdx.x;

    if (bid < 4096) {  // ---- dist_pack
        size_t i = ((size_t)bid * 256 + tid) * 8;
        int4 a = *(const int4*)(dist + i);
        int4 b = *(const int4*)(dist + i + 4);
        unsigned c0 = (unsigned)min(max(a.x, 0), 31) | ((unsigned)min(max(a.y, 0), 31) << 8) |
                      ((unsigned)min(max(a.z, 0), 31) << 16) | ((unsigned)min(max(a.w, 0), 31) << 24);
        unsigned c1 = (unsigned)min(max(b.x, 0), 31) | ((unsigned)min(max(b.y, 0), 31) << 8) |
                      ((unsigned)min(max(b.z, 0), 31) << 16) | ((unsigned)min(max(b.w, 0), 31) << 24);
        *(uint2*)(g_dist8 + i) = make_uint2(c0, c1);
    } else if (bid < 5632) {  // ---- conv_x
        size_t i = ((size_t)(bid - 4096) * 256 + tid) * 8;
        float4 a = *(const float4*)(x + i);
        float4 b = *(const float4*)(x + i + 4);
        __half2* d = (__half2*)(g_xh + i);
        d[0] = __floats2half2_rn(a.x, a.y);
        d[1] = __floats2half2_rn(a.z, a.w);
        d[2] = __floats2half2_rn(b.x, b.y);
        d[3] = __floats2half2_rn(b.z, b.w);
    } else if (bid < 7936) {  // ---- wtrans (both weights)
        const int idx = bid - 5632;
        const float* src;
        __half* dst;
        int N, n0, k0;
        if (idx < 1728) { src = w1; dst = g_wt;  N = 2304; n0 = (idx % 72) * 32; k0 = (idx / 72) * 32; }
        else            { src = w2; dst = g_w2t; N = 768;  n0 = ((idx - 1728) % 24) * 32; k0 = ((idx - 1728) / 24) * 32; }
        const int tx = tid & 31, ty = tid >> 5;
        for (int i = ty; i < 32; i += 8)
            t[i][tx] = __float2half(src[(size_t)(k0 + i) * N + n0 + tx]);
        __syncthreads();
        for (int i = ty; i < 32; i += 8)
            dst[(size_t)(n0 + i) * 768 + k0 + tx] = t[tx][i];
    } else {  // ---- mask_prep (1 block)
        int ok_int = 1, ok_flt = 1;
        for (int i = tid; i < 1024; i += 256) {
            unsigned int v = mw[i];
            if (v != 0u && v != 1u) ok_int = 0;
            if (v != 0u && v != 0x3F800000u) ok_flt = 0;
        }
        ok_int = __syncthreads_and(ok_int);
        ok_flt = __syncthreads_and(ok_flt);
        if (ok_int) {
            const int* m = (const int*)mw;
            for (int i = tid; i < 4096; i += 256) g_mneg[i] = m[i] ? -1e30f : 0.0f;
        } else if (ok_flt) {
            const float* m = (const float*)mw;
            for (int i = tid; i < 4096; i += 256) g_mneg[i] = (m[i] != 0.0f) ? -1e30f : 0.0f;
        } else {
            const unsigned char* m = (const unsigned char*)mw;
            for (int i = tid; i < 4096; i += 256) g_mneg[i] = m[i] ? -1e30f : 0.0f;
        }
    }
}

// =============================================================================
// Kernel 1: fp16 GEMM, triple-buffered cp.async (validated R16)
// =============================================================================
static constexpr int GEMM_SMEM = 61440;

__global__ __launch_bounds__(256) void gemm_fp16(const float* __restrict__ Bv,
                                                 float* __restrict__ outp,
                                                 int N, int mode) {
    const __half *A, *Wt;
    if (mode == 0) { A = g_xh; Wt = g_wt; }     // device-side symbols (R7 lesson)
    else           { A = g_aoh; Wt = g_w2t; }
    extern __shared__ char smem[];
    const int tid = threadIdx.x, w = tid >> 5, l = tid & 31;
    const int gid = l >> 2, tig = l & 3;
    const int wm = w >> 2, wn = w & 3;
    const int bM = blockIdx.y * 128, bN = blockIdx.x * 128;
    const uint32_t sb_a = smem_u32(smem);
    const uint32_t sb_b = sb_a + 30720;

    auto stage = [&](int k0, int buf) {
#pragma unroll
        for (int j = 0; j < 2; j++) {
            int c = tid + j * 256, r = c >> 2, o = (c & 3) * 16;
            cpa16(sb_a + buf * 10240 + r * 80 + o,
                  (const char*)(A + (size_t)(bM + r) * 768) + k0 * 2 + o);
            cpa16(sb_b + buf * 10240 + r * 80 + o,
                  (const char*)(Wt + (size_t)(bN + r) * 768) + k0 * 2 + o);
        }
    };

    float acc[4][4][4];
#pragma unroll
    for (int mi = 0; mi < 4; mi++)
#pragma unroll
        for (int ni = 0; ni < 4; ni++)
#pragma unroll
            for (int j = 0; j < 4; j++) acc[mi][ni][j] = 0.f;

    const uint32_t prowA = (l & 7) + ((l >> 3) & 1) * 8;
    const uint32_t pcolA = ((l >> 4) & 1) * 16;
    const uint32_t rowB = (l & 7) + ((l >> 4) & 1) * 8;
    const uint32_t colB = ((l >> 3) & 1) * 16;

    stage(0, 0);
    CP_COMMIT();
    stage(32, 1);
    CP_COMMIT();

    for (int ks = 0; ks < 24; ks++) {
        if (ks < 23) CP_WAIT1(); else CP_WAIT0();
        __syncthreads();
        if (ks < 22) { stage((ks + 2) * 32, (ks + 2) % 3); CP_COMMIT(); }
        const int buf = ks % 3;
        const uint32_t abase = sb_a + buf * 10240;
        const uint32_t bbase = sb_b + buf * 10240;

#pragma unroll
        for (int kk = 0; kk < 2; kk++) {
            uint32_t Af[4][4], Bf[2][4];
#pragma unroll
            for (int mi = 0; mi < 4; mi++)
                ldsm4(Af[mi], abase + (wm * 64 + mi * 16 + prowA) * 80 + kk * 32 + pcolA);
#pragma unroll
            for (int bi = 0; bi < 2; bi++)
                ldsm4(Bf[bi], bbase + (wn * 32 + bi * 16 + rowB) * 80 + kk * 32 + colB);
#pragma unroll
            for (int mi = 0; mi < 4; mi++) {
                mma16(acc[mi][0], Af[mi], &Bf[0][0]);
                mma16(acc[mi][1], Af[mi], &Bf[0][2]);
                mma16(acc[mi][2], Af[mi], &Bf[1][0]);
                mma16(acc[mi][3], Af[mi], &Bf[1][2]);
            }
        }
    }

#pragma unroll
    for (int ni = 0; ni < 4; ni++) {
        const int col0 = bN + wn * 32 + ni * 8 + tig * 2;
        const float b0 = Bv[col0], b1 = Bv[col0 + 1];
        if (mode == 0) {
            const int which = col0 / 768;
            const int rem = col0 % 768;
            const int hh = rem / 64, hd0 = rem % 64;
            __half* dst = (which == 0) ? g_q : (which == 1 ? g_k : g_v);
            const float qs = (which == 0) ? 0.125f : 1.0f;
#pragma unroll
            for (int mi = 0; mi < 4; mi++) {
                const int row = bM + wm * 64 + mi * 16 + gid;
                const int bidx = row >> 11, n = row & 2047;
                __half* p = dst + ((((size_t)bidx * 12 + hh) * 2048 + n) * 64 + hd0);
                *(__half2*)p =
                    __floats2half2_rn((acc[mi][ni][0] + b0) * qs, (acc[mi][ni][1] + b1) * qs);
                const int row2 = row + 8;
                const int bidx2 = row2 >> 11, n2 = row2 & 2047;
                __half* p2 = dst + ((((size_t)bidx2 * 12 + hh) * 2048 + n2) * 64 + hd0);
                *(__half2*)p2 =
                    __floats2half2_rn((acc[mi][ni][2] + b0) * qs, (acc[mi][ni][3] + b1) * qs);
            }
        } else {
#pragma unroll
            for (int mi = 0; mi < 4; mi++) {
                const int row = bM + wm * 64 + mi * 16 + gid;
                *(float2*)(outp + (size_t)row * 768 + col0) =
                    make_float2(acc[mi][ni][0] + b0, acc[mi][ni][1] + b1);
                *(float2*)(outp + (size_t)(row + 8) * 768 + col0) =
                    make_float2(acc[mi][ni][2] + b0, acc[mi][ni][3] + b1);
            }
        }
    }
}

// =============================================================================
// Kernel 1b: transpose V (half) -> g_vt [B,H,64,N] (validated R14)
// =============================================================================
__global__ __launch_bounds__(256) void v_transpose() {
    __shared__ __half smh[64 * 66];
    const int n0 = blockIdx.x * 64;
    const int bh = blockIdx.y;
    const __half2* s2 = (const __half2*)(g_v + ((size_t)bh * 2048 + n0) * 64);
    for (int v = threadIdx.x; v < 2048; v += 256) {
        int i = v >> 5, d2 = v & 31;
        __half2 h = s2[i * 32 + d2];
        smh[(2 * d2) * 66 + i] = __low2half(h);
        smh[(2 * d2 + 1) * 66 + i] = __high2half(h);
    }
    __syncthreads();
    __half2* d2p = (__half2*)(g_vt + (size_t)bh * 64 * 2048 + n0);
    for (int v = threadIdx.x; v < 2048; v += 256) {
        int d = v >> 5, j = v & 31;
        d2p[(size_t)d * 1024 + j] = __halves2half2(smh[d * 66 + 2 * j], smh[d * 66 + 2 * j + 1]);
    }
}

// =============================================================================
// Kernel 2: fp16 flash attention, split-K — R17 softmax LDS fixes:
//  (1) Ds pitch 64 -> 80 B (20-word pitch, bank set {0,20,8,28,16,4,24,12}:
//      conflict-free byte gathers; was 4-way conflicted at pitch 64)
//  (2) bias_table gather via register + __shfl_sync (zero LDS, identical values)
// =============================================================================
static constexpr int VT_REL = 9216;
static constexpr int MNG_REL = 18432;
static constexpr int STG_SZ = 18688;
static constexpr int DS_OFF = 37376;          // dist [128 rows][80 B pitch] = 10240
static constexpr int PS_OFF = 47616;          // P half [128][72] = 18432 B
static constexpr int ATTN_SMEM = 66048;       // 2 CTAs/SM

__global__ __launch_bounds__(256, 2) void attn_mma(const float* __restrict__ bias_table) {
    extern __shared__ char smem[];
    const uint32_t sb = smem_u32(smem);
    unsigned char* Ds = (unsigned char*)(smem + DS_OFF);
    char* Psb = smem + PS_OFF;

    const int tid = threadIdx.x, w = tid >> 5, l = tid & 31;
    const int gid = l >> 2, tig = l & 3;
    const int qt = blockIdx.x, h = blockIdx.y;
    const int b = blockIdx.z >> 1, sp = blockIdx.z & 1;
    const int kt0 = sp * 16;
    const size_t bh = (size_t)b * 12 + h;

    const char* kgbase = (const char*)(g_k + bh * 2048 * 64);
    const char* vgbase = (const char*)(g_vt + bh * 64 * 2048);
    const unsigned char* dgbase = g_dist8 + (size_t)(b * 2048 + qt * 128) * 2048;

    auto stage_kv = [&](int kt, int buf) {
        const uint32_t base = sb + buf * STG_SZ;
#pragma unroll
        for (int j = 0; j < 2; j++) {
            int c = tid + j * 256, r = c >> 3, o = (c & 7) * 16;
            cpa16(base + r * 144 + o, kgbase + (size_t)(kt * 64 + r) * 128 + o);
        }
#pragma unroll
        for (int j = 0; j < 2; j++) {
            int c = tid + j * 256, r = c >> 3, o = (c & 7) * 16;
            cpa16(base + VT_REL + r * 144 + o, vgbase + (size_t)r * 4096 + kt * 128 + o);
        }
        if (tid < 16) cpa16(base + MNG_REL + tid * 16, g_mneg + b * 2048 + kt * 64 + tid * 4);
    };
    auto stage_dm = [&](int kt) {  // warp-local dist rows, 80 B pitch
#pragma unroll
        for (int j = 0; j < 2; j++) {
            int c = l + j * 32, r = w * 16 + (c >> 2), o = (c & 3) * 16;
            cpa16(sb + DS_OFF + r * 80 + o, dgbase + (size_t)r * 2048 + kt * 64 + o);
        }
    };

    // ---- Q fragments (fp16, register-resident; validated R14)
    uint32_t Qa[4][4];
    {
        const char* qb = (const char*)(g_q + (bh * 2048 + qt * 128 + w * 16) * 64);
#pragma unroll
        for (int s = 0; s < 4; s++) {
            const int o = s * 32 + tig * 4;
            Qa[s][0] = *(const uint32_t*)(qb + gid * 128 + o);
            Qa[s][1] = *(const uint32_t*)(qb + (gid + 8) * 128 + o);
            Qa[s][2] = *(const uint32_t*)(qb + gid * 128 + o + 16);
            Qa[s][3] = *(const uint32_t*)(qb + (gid + 8) * 128 + o + 16);
        }
    }
    // R17: bias table lives in registers; gathered by __shfl (lane l holds bt[l])
    const float btr = bias_table[l * 12 + h];

    const uint32_t rowB = (l & 7) + ((l >> 4) & 1) * 8;
    const uint32_t colB = ((l >> 3) & 1) * 16;
    const uint32_t kvoff = rowB * 144 + colB;
    const uint32_t prowA = (l & 7) + ((l >> 3) & 1) * 8;
    const uint32_t pcolA = ((l >> 4) & 1) * 16;
    const uint32_t pbase = sb + PS_OFF + (w * 16 + prowA) * 144 + pcolA;

    float O[8][4];
#pragma unroll
    for (int n = 0; n < 8; n++)
#pragma unroll
        for (int j = 0; j < 4; j++) O[n][j] = 0.f;
    float lsum0 = 0.f, lsum1 = 0.f;

    stage_kv(kt0, 0);
    stage_dm(kt0);
    CP_COMMIT();

    for (int kt = kt0; kt < kt0 + 16; kt++) {
        CP_WAIT0();
        __syncthreads();
        if (kt < kt0 + 15) { stage_kv(kt + 1, (kt + 1) & 1); CP_COMMIT(); }

        const uint32_t stg = sb + (kt & 1) * STG_SZ;
        const uint32_t kbase = stg + kvoff;
        const uint32_t vbase = stg + VT_REL + kvoff;
        const float* mng = (const float*)(smem + (kt & 1) * STG_SZ + MNG_REL);

        // ---- S = Q @ K^T
        float S[8][4];
#pragma unroll
        for (int n = 0; n < 8; n++)
#pragma unroll
            for (int j = 0; j < 4; j++) S[n][j] = 0.f;
#pragma unroll
        for (int s = 0; s < 4; s++) {
            uint32_t Bf[4][4];
#pragma unroll
            for (int p = 0; p < 4; p++) ldsm4(Bf[p], kbase + p * 2304 + s * 32);
#pragma unroll
            for (int p = 0; p < 4; p++) {
                mma16(S[2 * p], Qa[s], &Bf[p][0]);
                mma16(S[2 * p + 1], Qa[s], &Bf[p][2]);
            }
        }

        // ---- bias (shfl gather) + mask + exp -> Ps
        const unsigned char* d0p = Ds + (size_t)(w * 16 + gid) * 80;
        const unsigned char* d1p = Ds + (size_t)(w * 16 + gid + 8) * 80;
        const int prow = w * 16 + gid;
#pragma unroll
        for (int n = 0; n < 8; n++) {
            const int c0 = n * 8 + tig * 2;
            const float mg0 = mng[c0], mg1 = mng[c0 + 1];
            float b00 = __shfl_sync(0xffffffffu, btr, d0p[c0]);
            float b01 = __shfl_sync(0xffffffffu, btr, d0p[c0 + 1]);
            float b10 = __shfl_sync(0xffffffffu, btr, d1p[c0]);
            float b11 = __shfl_sync(0xffffffffu, btr, d1p[c0 + 1]);
            float p00 = __expf(S[n][0] + b00 + mg0);
            float p01 = __expf(S[n][1] + b01 + mg1);
            float p10 = __expf(S[n][2] + b10 + mg0);
            float p11 = __expf(S[n][3] + b11 + mg1);
            __half2 h0 = __floats2half2_rn(p00, p01);
            __half2 h1 = __floats2half2_rn(p10, p11);
            float2 f0 = __half22float2(h0), f1 = __half22float2(h1);
            lsum0 += f0.x + f0.y;
            lsum1 += f1.x + f1.y;
            *(__half2*)(Psb + prow * 144 + c0 * 2) = h0;
            *(__half2*)(Psb + (prow + 8) * 144 + c0 * 2) = h1;
        }
        __syncwarp();
        if (kt < kt0 + 15) { stage_dm(kt + 1); CP_COMMIT(); }

        // ---- O += P @ V
#pragma unroll
        for (int kk = 0; kk < 4; kk++) {
            uint32_t Pa[4];
            ldsm4(Pa, pbase + kk * 32);
            uint32_t Vf[4][4];
#pragma unroll
            for (int p = 0; p < 4; p++) ldsm4(Vf[p], vbase + p * 2304 + kk * 32);
#pragma unroll
            for (int p = 0; p < 4; p++) {
                mma16(O[2 * p], Pa, &Vf[p][0]);
                mma16(O[2 * p + 1], Pa, &Vf[p][2]);
            }
        }
    }

    // ---- epilogue: quad-reduce lsum, write unnormalized partials (R13 scheme)
    lsum0 += __shfl_xor_sync(0xffffffffu, lsum0, 1);
    lsum0 += __shfl_xor_sync(0xffffffffu, lsum0, 2);
    lsum1 += __shfl_xor_sync(0xffffffffu, lsum1, 1);
    lsum1 += __shfl_xor_sync(0xffffffffu, lsum1, 2);
    const size_t rbase = bh * 2048 + qt * 128 + w * 16;
    float* dst = g_part + (size_t)sp * 3145728 + rbase * 64;
#pragma unroll
    for (int n = 0; n < 8; n++) {
        const int c0 = n * 8 + tig * 2;
        *(float2*)&dst[gid * 64 + c0] = make_float2(O[n][0], O[n][1]);
        *(float2*)&dst[(gid + 8) * 64 + c0] = make_float2(O[n][2], O[n][3]);
    }
    if (tig == 0) {
        g_lsum[sp * 49152 + rbase + gid] = lsum0;
        g_lsum[sp * 49152 + rbase + gid + 8] = lsum1;
    }
}

// =============================================================================
// Kernel 2b: combine split-K partials -> HALF g_aoh (validated R15)
// =============================================================================
__global__ void combine_k() {
    const int i = (blockIdx.x * 256 + threadIdx.x) * 4;
    const int b = i / (2048 * 768);
    const int rem = i - b * 2048 * 768;
    const int n = rem / 768;
    const int c = rem - n * 768;
    const int h = c >> 6, hd = c & 63;
    const size_t row = ((size_t)(b * 12 + h)) * 2048 + n;
    const size_t p = row * 64 + hd;
    float4 o1 = *(const float4*)(g_part + p);
    float4 o2 = *(const float4*)(g_part + 3145728 + p);
    const float inv = 1.0f / (g_lsum[row] + g_lsum[49152 + row]);
    __half2* d = (__half2*)(g_aoh + i);
    d[0] = __floats2half2_rn((o1.x + o2.x) * inv, (o1.y + o2.y) * inv);
    d[1] = __floats2half2_rn((o1.z + o2.z) * inv, (o1.w + o2.w) * inv);
}

// =============================================================================
extern "C" void kernel_launch(void* const* d_in, const int* in_sizes, int n_in,
                              void* d_out, int out_size) {
    const float* x         = (const float*)d_in[0];
    const int* dist        = (const int*)d_in[1];
    const unsigned int* mk = (const unsigned int*)d_in[2];
    const float* qkv_w     = (const float*)d_in[3];
    const float* qkv_b     = (const float*)d_in[4];
    const float* out_w     = (const float*)d_in[5];
    const float* out_b     = (const float*)d_in[6];
    const float* bt        = (const float*)d_in[7];
    float* out             = (float*)d_out;

    prep_all<<<7937, 256>>>(dist, x, qkv_w, out_w, mk);

    cudaFuncSetAttribute(gemm_fp16, cudaFuncAttributeMaxDynamicSharedMemorySize, GEMM_SMEM);
    dim3 g1(18, 32);
    gemm_fp16<<<g1, 256, GEMM_SMEM>>>(qkv_b, nullptr, 2304, 0);

    dim3 gt(32, 24);
    v_transpose<<<gt, 256>>>();

    cudaFuncSetAttribute(attn_mma, cudaFuncAttributeMaxDynamicSharedMemorySize, ATTN_SMEM);
    dim3 g2(16, 12, 4);
    attn_mma<<<g2, 256, ATTN_SMEM>>>(bt);

    combine_k<<<3072, 256>>>();

    dim3 g3(6, 32);
    gemm_fp16<<<g3, 256, GEMM_SMEM>>>(out_b, out, 768, 1);
}